// round 12
// baseline (speedup 1.0000x reference)
#include <cuda_runtime.h>
#include <cuda_fp16.h>
#include <math.h>

#define HD 128
#define NB 16     // batches
#define NV 4      // vocab
#define NL 6      // layers
#define MAXN 20000
#define MAXE 600000

#define WCHUNK 2112            // words per weight chunk image (32 groups * 66)
#define WSTAGE (4 * WCHUNK)    // 8448 words per 128x128 weight

// ---------------- scratch (static device allocs; cudaMalloc is banned) -----
__device__ float g_hV[MAXN * HD];
__device__ float g_agg[MAXN * HD];
__device__ float g_ffn[MAXN * 4 * HD];
__device__ float g_xvs[MAXN * HD];
__device__ float g_xvd[MAXN * HD];
__device__ float g_deg[MAXN];
__device__ float g_pool[NB * HD];
__device__ float g_pcnt[NB];
__device__ __align__(16) __half g_hEh[(size_t)MAXE * HD];          // fp16 hE
__device__ __align__(16) unsigned g_wfrag[NL * 2 * WSTAGE];        // W1a/W2 frag images

// ---------------- tiny utility kernels -------------------------------------
__global__ void zero_kernel(float* __restrict__ p, int n) {
    int i = blockIdx.x * blockDim.x + threadIdx.x;
    if (i < n) p[i] = 0.f;
}

__global__ void copy_kernel(float* __restrict__ dst, const float* __restrict__ src, int n) {
    int i = blockIdx.x * blockDim.x + threadIdx.x;
    if (i < n) dst[i] = src[i];
}

__global__ void deg_kernel(const int* __restrict__ src, float* __restrict__ deg, int E) {
    int i = blockIdx.x * blockDim.x + threadIdx.x;
    if (i < E) atomicAdd(&deg[src[i]], 1.f);
}

__global__ void convert_hE_kernel(const float* __restrict__ hE,
                                  __half2* __restrict__ out, int n2) {
    int i = blockIdx.x * blockDim.x + threadIdx.x;
    if (i < n2) {
        float2 f = ((const float2*)hE)[i];
        out[i] = __floats2half2_rn(f.x, f.y);
    }
}

// ---------------- fp16 + fragment-major helpers -----------------------------
__device__ __forceinline__ unsigned h2u(float lo, float hi) {
    __half2 h = __floats2half2_rn(lo, hi);
    return *(unsigned*)&h;
}

__device__ __forceinline__ void mma_f16(float c[4],
                                        unsigned a0, unsigned a1, unsigned a2, unsigned a3,
                                        unsigned b0, unsigned b1) {
    asm volatile(
        "mma.sync.aligned.m16n8k16.row.col.f32.f16.f16.f32 "
        "{%0,%1,%2,%3}, {%4,%5,%6,%7}, {%8,%9}, {%0,%1,%2,%3};"
        : "+f"(c[0]), "+f"(c[1]), "+f"(c[2]), "+f"(c[3])
        : "r"(a0), "r"(a1), "r"(a2), "r"(a3), "r"(b0), "r"(b1));
}

// ---- A chunk (128 rows x 32 k f32) -> 16 groups of half2 words, pitch 132
__device__ __forceinline__ void ldg_A(float4 v[4], const float* __restrict__ A,
                                      size_t lda, int row0, int M, int kglob0, int tid)
{
#pragma unroll
    for (int it = 0; it < 4; ++it) {
        int item = tid + it * 256;
        int row = item >> 3, q = item & 7;
        v[it] = make_float4(0.f, 0.f, 0.f, 0.f);
        if (row0 + row < M)
            v[it] = *(const float4*)(A + (size_t)(row0 + row) * lda + kglob0 + q * 4);
    }
}

__device__ __forceinline__ void sts_A_h(unsigned* __restrict__ As, const float4 v[4], int tid)
{
#pragma unroll
    for (int it = 0; it < 4; ++it) {
        int item = tid + it * 256;
        int row = item >> 3, q = item & 7;
        int g = ((row >> 4) << 1) + (q >> 2);
        int pk0 = (q & 3) * 2;
        int pk1 = pk0 + 1;
        int off0 = ((((row & 7) << 2) | (pk0 & 3)) << 2) + ((row >> 3) & 1) + (((pk0 >> 2) & 1) << 1);
        int off1 = ((((row & 7) << 2) | (pk1 & 3)) << 2) + ((row >> 3) & 1) + (((pk1 >> 2) & 1) << 1);
        As[g * 132 + off0] = h2u(v[it].x, v[it].y);
        As[g * 132 + off1] = h2u(v[it].z, v[it].w);
    }
}

// ---- A chunk from fp16 row-major hE (128 rows x 32 k halfs -> 2 uint4/thread)
__device__ __forceinline__ void ldg_Ah(uint4 v[2], const uint4* __restrict__ hEh,
                                       int e0, int E, int kc, int tid)
{
#pragma unroll
    for (int it = 0; it < 2; ++it) {
        int item = tid + it * 256;
        int r = item >> 2, jq = item & 3;   // jq: quad of 4 half2 (pk 4jq..4jq+3)
        v[it] = make_uint4(0u, 0u, 0u, 0u);
        if (e0 + r < E)
            v[it] = hEh[(size_t)(e0 + r) * 16 + kc * 4 + jq];
    }
}

__device__ __forceinline__ void sts_Ah(unsigned* __restrict__ As, const uint4 v[2], int tid)
{
#pragma unroll
    for (int it = 0; it < 2; ++it) {
        int item = tid + it * 256;
        int r = item >> 2, jq = item & 3;
        int g = ((r >> 4) << 1) + (jq >> 1);
        int base = g * 132 + ((r & 7) << 4) + ((r >> 3) & 1) + ((jq & 1) << 1);
        As[base + 0]  = v[it].x;
        As[base + 4]  = v[it].y;
        As[base + 8]  = v[it].z;
        As[base + 12] = v[it].w;
    }
}

// ---- B chunk (32 k x 128 n f32) -> 32 groups, pitch 66
__device__ __forceinline__ void ldg_Bh(float4 v0[2], float4 v1[2],
                                       const float* __restrict__ B, size_t ldb,
                                       int kglob0, int n0, int tid)
{
#pragma unroll
    for (int it = 0; it < 2; ++it) {
        int item = tid + it * 256;
        int p = item >> 5, q = item & 31;
        const float* base = B + (size_t)(kglob0 + 2 * p) * ldb + n0 + q * 4;
        v0[it] = *(const float4*)base;
        v1[it] = *(const float4*)(base + ldb);
    }
}

__device__ __forceinline__ void sts_Bh(unsigned* __restrict__ Bs,
                                       const float4 v0[2], const float4 v1[2], int tid)
{
#pragma unroll
    for (int it = 0; it < 2; ++it) {
        int item = tid + it * 256;
        int p = item >> 5, q = item & 31;
        int gb = (p >> 3) * 16 + (q >> 1);
        int pk = p & 7;
        int comp = (pk >> 2) & 1;
        const float* a = (const float*)&v0[it];
        const float* b = (const float*)&v1[it];
#pragma unroll
        for (int j = 0; j < 4; ++j) {
            int lane = ((((q & 1) << 2) + j) << 2) + (pk & 3);
            Bs[gb * 66 + lane * 2 + comp] = h2u(a[j], b[j]);
        }
    }
}

// ---- raw weight-image chunk copy (528 uint4 = 2112 words)
__device__ __forceinline__ void ldg_W(uint4 v[3], const uint4* __restrict__ W, int tid)
{
    v[0] = W[tid];
    v[1] = W[tid + 256];
    v[2] = (tid < 16) ? W[tid + 512] : make_uint4(0u, 0u, 0u, 0u);
}

__device__ __forceinline__ void sts_W(unsigned* __restrict__ Bs, const uint4 v[3], int tid)
{
    *(uint4*)(Bs + 4 * tid)         = v[0];
    *(uint4*)(Bs + 4 * (tid + 256)) = v[1];
    if (tid < 16) *(uint4*)(Bs + 4 * (tid + 512)) = v[2];
}

// build fragment-major fp16 weight images: block = l*8 + stage*4 + chunk
__global__ void convert_w_kernel(const float* __restrict__ W1,
                                 const float* __restrict__ W2all,
                                 unsigned* __restrict__ wfrag)
{
    int b = blockIdx.x;
    int l = b >> 3, stage = (b >> 2) & 1, kc = b & 3;
    const float* W = stage ? (W2all + (size_t)l * HD * HD)
                           : (W1 + (size_t)l * 3 * HD * HD);
    unsigned* dst = wfrag + ((size_t)l * 2 + stage) * WSTAGE + kc * WCHUNK;
    float4 v0[2], v1[2];
    ldg_Bh(v0, v1, W, HD, kc * 32, 0, threadIdx.x);
    sts_Bh(dst, v0, v1, threadIdx.x);
}

// one 32-k chunk (2 ktile16) of warp-tile 64x32 fp16 mma
__device__ __forceinline__ void mma_chunk_h(float acc[4][4][4],
                                            const unsigned* __restrict__ Af, int mg0, int gs, int gk0,
                                            const unsigned* __restrict__ Bs, int ng0, int lane)
{
#pragma unroll
    for (int kt = 0; kt < 2; ++kt) {
        uint4 a[4]; uint2 b[4];
#pragma unroll
        for (int mi = 0; mi < 4; ++mi)
            a[mi] = *(const uint4*)&Af[((mg0 + mi) * gs + gk0 + kt) * 132 + lane * 4];
#pragma unroll
        for (int ni = 0; ni < 4; ++ni)
            b[ni] = *(const uint2*)&Bs[((kt << 4) + ng0 + ni) * 66 + lane * 2];
#pragma unroll
        for (int mi = 0; mi < 4; ++mi)
#pragma unroll
            for (int ni = 0; ni < 4; ++ni)
                mma_f16(acc[mi][ni], a[mi].x, a[mi].y, a[mi].z, a[mi].w,
                        b[ni].x, b[ni].y);
    }
}

#define ACC_ZERO(acc) \
    _Pragma("unroll") for (int mi = 0; mi < 4; ++mi) \
    _Pragma("unroll") for (int ni = 0; ni < 4; ++ni) \
    _Pragma("unroll") for (int j = 0; j < 4; ++j) acc[mi][ni][j] = 0.f;

// ---------------- fused edge MLP (2 stages fp16; W3 hoisted) ----------------
#define WB_WORDS WSTAGE            // 8448 = W1a resident; == Cs (64 groups * 132)
#define CHUNK_WORDS 2112           // streamed chunk
#define EDGE_SMEM ((WB_WORDS + 2 * CHUNK_WORDS + 256) * 4)
#define GEMM_SMEM ((4 * CHUNK_WORDS) * 4)
#define GEMMLN_SMEM ((4 * CHUNK_WORDS + 2 * 128 * 4) * 4)

__global__ __launch_bounds__(256, 2)
void edge_mlp_tc(const uint4* __restrict__ hEh,
                 const int* __restrict__ esrc,
                 const int* __restrict__ edst,
                 const float* __restrict__ XVs,
                 const float* __restrict__ XVd,
                 const unsigned* __restrict__ wfrag,   // [W1a image | W2 image]
                 const float* __restrict__ b1, const float* __restrict__ b2,
                 float* __restrict__ agg, int E)
{
    extern __shared__ unsigned smem_u[];
    unsigned* WB = smem_u;                  // W1a resident; later Cs
    unsigned* Asb[2] = { WB + WB_WORDS, WB + WB_WORDS + CHUNK_WORDS };
    int* s_src = (int*)(WB + WB_WORDS + 2 * CHUNK_WORDS);
    int* s_dst = s_src + 128;

    const int tid = threadIdx.x;
    const int lane = tid & 31;
    const int wid = tid >> 5;
    const int mrow0 = (wid >> 2) * 64;
    const int ncol0 = (wid & 3) * 32;
    const int mg0 = mrow0 >> 4;
    const int ng0 = ncol0 >> 3;
    const int lq = lane >> 2;
    const int lr = lane & 3;
    const int e0 = blockIdx.x * 128;

    if (tid < 128) {
        int e = e0 + tid;
        s_src[tid] = (e < E) ? esrc[e] : -1;
        s_dst[tid] = (e < E) ? edst[e] : -1;
    }

    uint4 vh[2];
    uint4 vw[3];
    float acc[4][4][4];

    // ================= stage 1: hE @ W1a (W resident, A ping-pong) ==========
    ACC_ZERO(acc);
    {   // raw copy W1a image (2112 uint4)
        const uint4* src = (const uint4*)wfrag;
        for (int i = tid; i < 2112; i += 256)
            *(uint4*)(WB + 4 * i) = src[i];
    }
    ldg_Ah(vh, hEh, e0, E, 0, tid);
    sts_Ah(Asb[0], vh, tid);
    __syncthreads();

#pragma unroll
    for (int kc = 0; kc < 4; ++kc) {
        if (kc < 3) ldg_Ah(vh, hEh, e0, E, kc + 1, tid);
        mma_chunk_h(acc, Asb[kc & 1], mg0, 2, 0, WB + kc * CHUNK_WORDS, ng0, lane);
        if (kc < 3) sts_Ah(Asb[(kc + 1) & 1], vh, tid);
        __syncthreads();
    }

    unsigned* Cs = WB;   // alias — all W1a reads are done
    const uint4* W2img = (const uint4*)(wfrag + WSTAGE);

    // prefetch W2 chunk 0 (lands while epilogue runs)
    ldg_W(vw, W2img, tid);

    // epilogue 1: + b1 + XVs[src] + XVd[dst], relu, half2 -> Cs (fp16 A-frag order)
#pragma unroll
    for (int ni = 0; ni < 4; ++ni) {
        int cb = ncol0 + ni * 8 + 2 * lr;
        int pk = cb >> 1;
        int gk = pk >> 3;
        int pkl = pk & 7;
        float b10 = b1[cb], b11 = b1[cb + 1];
#pragma unroll
        for (int mi = 0; mi < 4; ++mi) {
#pragma unroll
            for (int h = 0; h < 2; ++h) {
                int r = mrow0 + mi * 16 + lq + h * 8;
                int ns = s_src[r], nd = s_dst[r];
                float w0 = 0.f, w1 = 0.f;
                if (ns >= 0) {
                    float2 xs = *(const float2*)(XVs + (size_t)ns * HD + cb);
                    float2 xd = *(const float2*)(XVd + (size_t)nd * HD + cb);
                    w0 = acc[mi][ni][h * 2 + 0] + b10 + xs.x + xd.x;
                    w1 = acc[mi][ni][h * 2 + 1] + b11 + xs.y + xd.y;
                }
                int idx = ((mg0 + mi) * 8 + gk) * 132
                        + (((lq << 2) | (pkl & 3)) << 2) + h + (((pkl >> 2) & 1) << 1);
                Cs[idx] = h2u(fmaxf(w0, 0.f), fmaxf(w1, 0.f));
            }
        }
    }
    sts_W(Asb[0], vw, tid);
    __syncthreads();

    // ================= stage 2: C1 @ W2 (W ping-pong, raw copies) ===========
    ACC_ZERO(acc);
#pragma unroll
    for (int kc = 0; kc < 4; ++kc) {
        if (kc < 3) ldg_W(vw, W2img + (kc + 1) * 528, tid);
        mma_chunk_h(acc, Cs, mg0, 8, kc * 2, Asb[kc & 1], ng0, lane);
        if (kc < 3) sts_W(Asb[(kc + 1) & 1], vw, tid);
        __syncthreads();
    }

    // epilogue 2 (final): relu(acc + b2) as half2 row-major (pitch 66) for scatter
#pragma unroll
    for (int ni = 0; ni < 4; ++ni) {
        int cb = ncol0 + ni * 8 + 2 * lr;
        int pk = cb >> 1;
        float b20 = b2[cb], b21 = b2[cb + 1];
#pragma unroll
        for (int mi = 0; mi < 4; ++mi) {
#pragma unroll
            for (int h = 0; h < 2; ++h) {
                int r = mrow0 + mi * 16 + lq + h * 8;
                Cs[r * 66 + pk] = h2u(fmaxf(acc[mi][ni][h * 2 + 0] + b20, 0.f),
                                      fmaxf(acc[mi][ni][h * 2 + 1] + b21, 0.f));
            }
        }
    }
    __syncthreads();

    // cooperative vector scatter of relu(C2): 128 rows x 32 float4
    for (int item = tid; item < 128 * 32; item += 256) {
        int row = item >> 5, q = item & 31;
        int node = s_src[row];
        if (node >= 0) {
            unsigned w0 = Cs[row * 66 + q * 2];
            unsigned w1 = Cs[row * 66 + q * 2 + 1];
            __half2 h0 = *(__half2*)&w0;
            __half2 h1 = *(__half2*)&w1;
            float* p = agg + (size_t)node * HD + q * 4;
            asm volatile("red.global.add.v4.f32 [%0], {%1,%2,%3,%4};"
                         :: "l"(p),
                            "f"(__low2float(h0)), "f"(__high2float(h0)),
                            "f"(__low2float(h1)), "f"(__high2float(h1))
                         : "memory");
        }
    }
}

// ---------------- fp16 node GEMM (128x128 tile, double-buffered) ------------
// epi 0: relu(A@B + bias); epi 2: A@B (no bias)
// blockIdx.z selects (B,C) or (B2,C2). zbuf (if set, z==0 only): zero rows of it.
__global__ __launch_bounds__(256, 2)
void gemm_tc(const float* __restrict__ A, const float* __restrict__ B,
             const float* __restrict__ B2,
             const float* __restrict__ bias,
             float* __restrict__ C, float* __restrict__ C2,
             float* __restrict__ zbuf,
             int M, int N, int K, int epi)
{
    extern __shared__ unsigned smem_u[];
    unsigned* Asb[2] = { smem_u, smem_u + CHUNK_WORDS };
    unsigned* Bsb[2] = { smem_u + 2 * CHUNK_WORDS, smem_u + 3 * CHUNK_WORDS };

    const int tid = threadIdx.x;
    const int lane = tid & 31;
    const int wid = tid >> 5;
    const int mrow0 = (wid >> 2) * 64;
    const int ncol0 = (wid & 3) * 32;
    const int mg0 = mrow0 >> 4;
    const int ng0 = ncol0 >> 3;
    const int lq = lane >> 2;
    const int lr = lane & 3;
    const int m0 = blockIdx.y * 128, n0 = blockIdx.x * 128;
    if (blockIdx.z) { B = B2; C = C2; zbuf = nullptr; }

    // fused zero of the scatter accumulator (rows of this CTA's tile)
    if (zbuf) {
        const float4 z4 = make_float4(0.f, 0.f, 0.f, 0.f);
        for (int item = tid; item < 128 * 32; item += 256) {
            int row = m0 + (item >> 5);
            if (row < M)
                *(float4*)(zbuf + (size_t)row * HD + (item & 31) * 4) = z4;
        }
    }

    float4 va[4];
    float4 v0[2], v1[2];
    float acc[4][4][4];
    ACC_ZERO(acc);

    const int nkc = K / 32;
    ldg_A(va, A, K, m0, M, 0, tid);
    ldg_Bh(v0, v1, B, N, 0, n0, tid);
    sts_A_h(Asb[0], va, tid);
    sts_Bh(Bsb[0], v0, v1, tid);
    __syncthreads();

    for (int kc = 0; kc < nkc; ++kc) {
        if (kc + 1 < nkc) {
            ldg_A(va, A, K, m0, M, (kc + 1) * 32, tid);
            ldg_Bh(v0, v1, B, N, (kc + 1) * 32, n0, tid);
        }
        mma_chunk_h(acc, Asb[kc & 1], mg0, 2, 0, Bsb[kc & 1], ng0, lane);
        if (kc + 1 < nkc) {
            sts_A_h(Asb[(kc + 1) & 1], va, tid);
            sts_Bh(Bsb[(kc + 1) & 1], v0, v1, tid);
        }
        __syncthreads();
    }

#pragma unroll
    for (int ni = 0; ni < 4; ++ni) {
        int c = n0 + ncol0 + ni * 8 + 2 * lr;
        float bb0 = (epi == 2) ? 0.f : bias[c];
        float bb1 = (epi == 2) ? 0.f : bias[c + 1];
#pragma unroll
        for (int mi = 0; mi < 4; ++mi) {
#pragma unroll
            for (int h = 0; h < 2; ++h) {
                int r = m0 + mrow0 + mi * 16 + lq + h * 8;
                if (r < M) {
                    float w0 = acc[mi][ni][h * 2 + 0] + bb0;
                    float w1 = acc[mi][ni][h * 2 + 1] + bb1;
                    if (epi == 0) { w0 = fmaxf(w0, 0.f); w1 = fmaxf(w1, 0.f); }
                    C[(size_t)r * N + c]     = w0;
                    C[(size_t)r * N + c + 1] = w1;
                }
            }
        }
    }
}

// ---------------- fused GEMM + residual + LayerNorm (N = 128 fixed) ---------
// out = LN(res + (A@B)*inv_deg + bias), register-resident LN.
__global__ __launch_bounds__(256, 2)
void gemm_ln(const float* __restrict__ A, const float* __restrict__ B,
             const float* __restrict__ bias, const float* __restrict__ res,
             const float* __restrict__ deg,
             const float* __restrict__ lng, const float* __restrict__ lnb,
             float* __restrict__ out, int M, int K)
{
    extern __shared__ unsigned smem_u[];
    unsigned* Asb[2] = { smem_u, smem_u + CHUNK_WORDS };
    unsigned* Bsb[2] = { smem_u + 2 * CHUNK_WORDS, smem_u + 3 * CHUNK_WORDS };
    float* s_sum = (float*)(smem_u + 4 * CHUNK_WORDS);  // [128][4]
    float* s_sqs = s_sum + 128 * 4;                     // [128][4]

    const int tid = threadIdx.x;
    const int lane = tid & 31;
    const int wid = tid >> 5;
    const int mrow0 = (wid >> 2) * 64;
    const int ncol0 = (wid & 3) * 32;
    const int mg0 = mrow0 >> 4;
    const int ng0 = ncol0 >> 3;
    const int lq = lane >> 2;
    const int lr = lane & 3;
    const int wc = wid & 3;
    const int m0 = blockIdx.y * 128;

    float4 va[4];
    float4 v0[2], v1[2];
    float acc[4][4][4];
    ACC_ZERO(acc);

    const int nkc = K / 32;
    ldg_A(va, A, K, m0, M, 0, tid);
    ldg_Bh(v0, v1, B, HD, 0, 0, tid);
    sts_A_h(Asb[0], va, tid);
    sts_Bh(Bsb[0], v0, v1, tid);
    __syncthreads();

    for (int kc = 0; kc < nkc; ++kc) {
        if (kc + 1 < nkc) {
            ldg_A(va, A, K, m0, M, (kc + 1) * 32, tid);
            ldg_Bh(v0, v1, B, HD, (kc + 1) * 32, 0, tid);
        }
        mma_chunk_h(acc, Asb[kc & 1], mg0, 2, 0, Bsb[kc & 1], ng0, lane);
        if (kc + 1 < nkc) {
            sts_A_h(Asb[(kc + 1) & 1], va, tid);
            sts_Bh(Bsb[(kc + 1) & 1], v0, v1, tid);
        }
        __syncthreads();
    }

    // x = res + acc*inv_deg + bias (in registers); publish per-(row,warp) partials
#pragma unroll
    for (int mi = 0; mi < 4; ++mi) {
#pragma unroll
        for (int h = 0; h < 2; ++h) {
            int r = mrow0 + mi * 16 + lq + h * 8;
            int rg = m0 + r;
            float ps = 0.f, pq = 0.f;
            if (rg < M) {
                float id = deg ? (1.f / fmaxf(deg[rg], 1.f)) : 1.f;
#pragma unroll
                for (int ni = 0; ni < 4; ++ni) {
                    int c = ncol0 + ni * 8 + 2 * lr;
                    float2 rr = *(const float2*)(res + (size_t)rg * HD + c);
                    float x0 = rr.x + acc[mi][ni][h * 2 + 0] * id + bias[c];
                    float x1 = rr.y + acc[mi][ni][h * 2 + 1] * id + bias[c + 1];
                    acc[mi][ni][h * 2 + 0] = x0;
                    acc[mi][ni][h * 2 + 1] = x1;
                    ps += x0 + x1;
                    pq += x0 * x0 + x1 * x1;
                }
            }
            ps += __shfl_xor_sync(0xffffffffu, ps, 1);
            pq += __shfl_xor_sync(0xffffffffu, pq, 1);
            ps += __shfl_xor_sync(0xffffffffu, ps, 2);
            pq += __shfl_xor_sync(0xffffffffu, pq, 2);
            if (lr == 0) {
                s_sum[r * 4 + wc] = ps;
                s_sqs[r * 4 + wc] = pq;
            }
        }
    }
    __syncthreads();

#pragma unroll
    for (int mi = 0; mi < 4; ++mi) {
#pragma unroll
        for (int h = 0; h < 2; ++h) {
            int r = mrow0 + mi * 16 + lq + h * 8;
            int rg = m0 + r;
            if (rg < M) {
                float s = s_sum[r * 4 + 0] + s_sum[r * 4 + 1]
                        + s_sum[r * 4 + 2] + s_sum[r * 4 + 3];
                float q = s_sqs[r * 4 + 0] + s_sqs[r * 4 + 1]
                        + s_sqs[r * 4 + 2] + s_sqs[r * 4 + 3];
                float mu = s * (1.f / HD);
                float var = q * (1.f / HD) - mu * mu;
                float inv = rsqrtf(var + 1e-5f);
#pragma unroll
                for (int ni = 0; ni < 4; ++ni) {
                    int c = ncol0 + ni * 8 + 2 * lr;
                    float2 o;
                    o.x = (acc[mi][ni][h * 2 + 0] - mu) * inv * lng[c]     + lnb[c];
                    o.y = (acc[mi][ni][h * 2 + 1] - mu) * inv * lng[c + 1] + lnb[c + 1];
                    *(float2*)(out + (size_t)rg * HD + c) = o;
                }
            }
        }
    }
}

// ---------------- pooling / heads ------------------------------------------
__global__ void pool_kernel(const float* __restrict__ hV, const int* __restrict__ batch_id,
                            float* __restrict__ pool, float* __restrict__ pcnt, int N)
{
    int i = blockIdx.x * blockDim.x + threadIdx.x;
    if (i < N * HD) {
        int n = i >> 7, c = i & 127;
        atomicAdd(&pool[batch_id[n] * HD + c], hV[i]);
    }
    if (i < N) atomicAdd(&pcnt[batch_id[i]], 1.f);
}

__global__ void head_kernel(const float* __restrict__ pool, const float* __restrict__ pcnt,
                            const float* __restrict__ P1, const float* __restrict__ P2,
                            const float* __restrict__ p2b, float* __restrict__ out)
{
    __shared__ float embs[NB * HD];
    __shared__ float t1[NB * HD];
    int tid = threadIdx.x;
    for (int i = tid; i < NB * HD; i += blockDim.x) {
        int bb = i >> 7;
        embs[i] = pool[i] / fmaxf(pcnt[bb], 1.f);
    }
    __syncthreads();
    for (int i = tid; i < NB * HD; i += blockDim.x) {
        int bb = i >> 7, j = i & 127;
        float s = 0.f;
        for (int k = 0; k < HD; k++) s += embs[bb * HD + k] * P1[k * HD + j];
        t1[i] = fmaxf(s, 0.f);
    }
    __syncthreads();
    for (int i = tid; i < NB * HD; i += blockDim.x) {
        int bb = i >> 7, j = i & 127;
        float s = p2b[j];
        for (int k = 0; k < HD; k++) s += t1[bb * HD + k] * P2[k * HD + j];
        out[i] = s;
    }
}

__global__ void logits_kernel(const float* __restrict__ hV, const int* __restrict__ S,
                              const float* __restrict__ R, const float* __restrict__ rb,
                              float* __restrict__ out, int N)
{
    __shared__ float Rs[HD * NV];
    __shared__ float rbs[NV];
    int tid = threadIdx.x;
    for (int i = tid; i < HD * NV; i += blockDim.x) Rs[i] = R[i];
    if (tid < NV) rbs[tid] = rb[tid];
    __syncthreads();
    int n = blockIdx.x * blockDim.x + tid;
    if (n < N) {
        float a0 = rbs[0], a1 = rbs[1], a2 = rbs[2], a3 = rbs[3];
        const float* h = hV + (size_t)n * HD;
#pragma unroll 8
        for (int k = 0; k < HD; k++) {
            float hv = h[k];
            a0 += hv * Rs[k * NV + 0];
            a1 += hv * Rs[k * NV + 1];
            a2 += hv * Rs[k * NV + 2];
            a3 += hv * Rs[k * NV + 3];
        }
        out[(size_t)n * NV + 0] = a0;
        out[(size_t)n * NV + 1] = a1;
        out[(size_t)n * NV + 2] = a2;
        out[(size_t)n * NV + 3] = a3;
        out[(size_t)N * NV + n] = (float)S[n];
    }
}

// ---------------- launch ----------------------------------------------------
extern "C" void kernel_launch(void* const* d_in, const int* in_sizes, int n_in,
                              void* d_out, int out_size)
{
    const float* h_V  = (const float*)d_in[0];
    const float* h_E  = (const float*)d_in[1];
    const int*   Eidx = (const int*)d_in[2];
    const int*   bid  = (const int*)d_in[3];
    const int*   S    = (const int*)d_in[4];
    const float* W1   = (const float*)d_in[5];
    const float* b1   = (const float*)d_in[6];
    const float* W2   = (const float*)d_in[7];
    const float* b2   = (const float*)d_in[8];
    const float* W3   = (const float*)d_in[9];
    const float* b3   = (const float*)d_in[10];
    const float* ln1g = (const float*)d_in[11];
    const float* ln1b = (const float*)d_in[12];
    const float* Wi   = (const float*)d_in[13];
    const float* bi   = (const float*)d_in[14];
    const float* Wo   = (const float*)d_in[15];
    const float* bo   = (const float*)d_in[16];
    const float* ln2g = (const float*)d_in[17];
    const float* ln2b = (const float*)d_in[18];
    const float* P1   = (const float*)d_in[19];
    const float* P2   = (const float*)d_in[20];
    const float* p2b  = (const float*)d_in[21];
    const float* R    = (const float*)d_in[22];
    const float* rb   = (const float*)d_in[23];

    const int N = in_sizes[0] / HD;
    const int E = in_sizes[2] / 2;
    const int* esrc = Eidx;
    const int* edst = Eidx + E;

    float *p_hV, *p_agg, *p_ffn, *p_xvs, *p_xvd, *p_deg, *p_pool, *p_pcnt;
    void *p_hEh, *p_wfrag;
    cudaGetSymbolAddress((void**)&p_hV,   g_hV);
    cudaGetSymbolAddress((void**)&p_agg,  g_agg);
    cudaGetSymbolAddress((void**)&p_ffn,  g_ffn);
    cudaGetSymbolAddress((void**)&p_xvs,  g_xvs);
    cudaGetSymbolAddress((void**)&p_xvd,  g_xvd);
    cudaGetSymbolAddress((void**)&p_deg,  g_deg);
    cudaGetSymbolAddress((void**)&p_pool, g_pool);
    cudaGetSymbolAddress((void**)&p_pcnt, g_pcnt);
    cudaGetSymbolAddress(&p_hEh,  g_hEh);
    cudaGetSymbolAddress(&p_wfrag, g_wfrag);

    cudaFuncSetAttribute(edge_mlp_tc,
                         cudaFuncAttributeMaxDynamicSharedMemorySize, EDGE_SMEM);
    cudaFuncSetAttribute(gemm_tc,
                         cudaFuncAttributeMaxDynamicSharedMemorySize, GEMM_SMEM);
    cudaFuncSetAttribute(gemm_ln,
                         cudaFuncAttributeMaxDynamicSharedMemorySize, GEMMLN_SMEM);

    copy_kernel<<<(N * HD + 255) / 256, 256>>>(p_hV, h_V, N * HD);

    zero_kernel<<<(N + 255) / 256, 256>>>(p_deg, N);
    deg_kernel<<<(E + 255) / 256, 256>>>(esrc, p_deg, E);

    // one-time fp16 precomputation: hE and fragment-major weight images
    convert_hE_kernel<<<(E * 64 + 255) / 256, 256>>>(h_E, (__half2*)p_hEh, E * 64);
    convert_w_kernel<<<NL * 8, 256>>>(W1, W2, (unsigned*)p_wfrag);

    const int edge_grid = (E + 127) / 128;
    const int mtiles = (N + 127) / 128;

    for (int l = 0; l < NL; ++l) {
        const float* W1l = W1 + (size_t)l * 3 * HD * HD;
        // fused pre-GEMMs (+ zero agg): XVs = hV @ W1[128:256], XVd = hV @ W1[256:384]
        gemm_tc<<<dim3(1, mtiles, 2), 256, GEMM_SMEM>>>(
            p_hV, W1l + (size_t)HD * HD, W1l + (size_t)2 * HD * HD,
            nullptr, p_xvs, p_xvd, p_agg, N, HD, HD, 2);

        edge_mlp_tc<<<edge_grid, 256, EDGE_SMEM>>>(
            (const uint4*)p_hEh, esrc, edst, p_xvs, p_xvd,
            (const unsigned*)p_wfrag + (size_t)l * 2 * WSTAGE,
            b1 + (size_t)l * HD, b2 + (size_t)l * HD,
            p_agg, E);
        // hV = LN(hV + (agg@W3)/deg + b3)
        gemm_ln<<<dim3(1, mtiles), 256, GEMMLN_SMEM>>>(
            p_agg, W3 + (size_t)l * HD * HD, b3 + (size_t)l * HD,
            p_hV, p_deg,
            ln1g + (size_t)l * HD, ln1b + (size_t)l * HD, p_hV, N, HD);
        // FFN up: relu(hV @ Wi + bi)
        gemm_tc<<<dim3(4, mtiles, 1), 256, GEMM_SMEM>>>(
            p_hV, Wi + (size_t)l * HD * 4 * HD, nullptr,
            bi + (size_t)l * 4 * HD, p_ffn, nullptr, nullptr, N, 4 * HD, HD, 0);
        // hV = LN(hV + ffn@Wo + bo)
        gemm_ln<<<dim3(1, mtiles), 256, GEMMLN_SMEM>>>(
            p_ffn, Wo + (size_t)l * 4 * HD * HD, bo + (size_t)l * HD,
            p_hV, nullptr,
            ln2g + (size_t)l * HD, ln2b + (size_t)l * HD, p_hV, N, 4 * HD);
    }

    zero_kernel<<<(NB * HD + 255) / 256, 256>>>(p_pool, NB * HD);
    zero_kernel<<<1, 32>>>(p_pcnt, NB);
    pool_kernel<<<(N * HD + 255) / 256, 256>>>(p_hV, bid, p_pool, p_pcnt, N);

    float* out = (float*)d_out;
    head_kernel<<<1, 256>>>(p_pool, p_pcnt, P1, P2, p2b,
                            out + (size_t)N * NV + N);
    logits_kernel<<<(N + 255) / 256, 256>>>(p_hV, S, R, rb, out, N);
}

// round 13
// speedup vs baseline: 1.0141x; 1.0141x over previous
#include <cuda_runtime.h>
#include <cuda_fp16.h>
#include <math.h>

#define HD 128
#define NB 16     // batches
#define NV 4      // vocab
#define NL 6      // layers
#define MAXN 20000
#define MAXE 600000

#define WCHUNK 2112            // words per weight chunk image (32 groups * 66)
#define WSTAGE (4 * WCHUNK)    // 8448 words per 128x128 weight

// ---------------- scratch (static device allocs; cudaMalloc is banned) -----
__device__ float g_hV[MAXN * HD];
__device__ float g_agg[MAXN * HD];
__device__ float g_ffn[MAXN * 4 * HD];
__device__ float g_xvs[MAXN * HD];
__device__ float g_xvd[MAXN * HD];
__device__ float g_deg[MAXN];
__device__ float g_pool[NB * HD];
__device__ float g_pcnt[NB];
__device__ __align__(16) unsigned g_wfrag[NL * 2 * WSTAGE];        // W1a/W2 frag images

// ---------------- tiny utility kernels -------------------------------------
__global__ void zero_kernel(float* __restrict__ p, int n) {
    int i = blockIdx.x * blockDim.x + threadIdx.x;
    if (i < n) p[i] = 0.f;
}

__global__ void copy_kernel(float* __restrict__ dst, const float* __restrict__ src, int n) {
    int i = blockIdx.x * blockDim.x + threadIdx.x;
    if (i < n) dst[i] = src[i];
}

__global__ void deg_kernel(const int* __restrict__ src, float* __restrict__ deg, int E) {
    int i = blockIdx.x * blockDim.x + threadIdx.x;
    if (i < E) atomicAdd(&deg[src[i]], 1.f);
}

// ---------------- fp16 + fragment-major helpers -----------------------------
__device__ __forceinline__ unsigned h2u(float lo, float hi) {
    __half2 h = __floats2half2_rn(lo, hi);
    return *(unsigned*)&h;
}

__device__ __forceinline__ void mma_f16(float c[4],
                                        unsigned a0, unsigned a1, unsigned a2, unsigned a3,
                                        unsigned b0, unsigned b1) {
    asm volatile(
        "mma.sync.aligned.m16n8k16.row.col.f32.f16.f16.f32 "
        "{%0,%1,%2,%3}, {%4,%5,%6,%7}, {%8,%9}, {%0,%1,%2,%3};"
        : "+f"(c[0]), "+f"(c[1]), "+f"(c[2]), "+f"(c[3])
        : "r"(a0), "r"(a1), "r"(a2), "r"(a3), "r"(b0), "r"(b1));
}

// ---- A chunk (128 rows x 32 k f32) -> 16 groups of half2 words, pitch 132
__device__ __forceinline__ void ldg_A(float4 v[4], const float* __restrict__ A,
                                      size_t lda, int row0, int M, int kglob0, int tid)
{
#pragma unroll
    for (int it = 0; it < 4; ++it) {
        int item = tid + it * 256;
        int row = item >> 3, q = item & 7;
        v[it] = make_float4(0.f, 0.f, 0.f, 0.f);
        if (row0 + row < M)
            v[it] = *(const float4*)(A + (size_t)(row0 + row) * lda + kglob0 + q * 4);
    }
}

__device__ __forceinline__ void sts_A_h(unsigned* __restrict__ As, const float4 v[4], int tid)
{
#pragma unroll
    for (int it = 0; it < 4; ++it) {
        int item = tid + it * 256;
        int row = item >> 3, q = item & 7;
        int g = ((row >> 4) << 1) + (q >> 2);
        int pk0 = (q & 3) * 2;
        int pk1 = pk0 + 1;
        int off0 = ((((row & 7) << 2) | (pk0 & 3)) << 2) + ((row >> 3) & 1) + (((pk0 >> 2) & 1) << 1);
        int off1 = ((((row & 7) << 2) | (pk1 & 3)) << 2) + ((row >> 3) & 1) + (((pk1 >> 2) & 1) << 1);
        As[g * 132 + off0] = h2u(v[it].x, v[it].y);
        As[g * 132 + off1] = h2u(v[it].z, v[it].w);
    }
}

// ---- B chunk (32 k x 128 n f32) -> 32 groups, pitch 66
__device__ __forceinline__ void ldg_Bh(float4 v0[2], float4 v1[2],
                                       const float* __restrict__ B, size_t ldb,
                                       int kglob0, int n0, int tid)
{
#pragma unroll
    for (int it = 0; it < 2; ++it) {
        int item = tid + it * 256;
        int p = item >> 5, q = item & 31;
        const float* base = B + (size_t)(kglob0 + 2 * p) * ldb + n0 + q * 4;
        v0[it] = *(const float4*)base;
        v1[it] = *(const float4*)(base + ldb);
    }
}

__device__ __forceinline__ void sts_Bh(unsigned* __restrict__ Bs,
                                       const float4 v0[2], const float4 v1[2], int tid)
{
#pragma unroll
    for (int it = 0; it < 2; ++it) {
        int item = tid + it * 256;
        int p = item >> 5, q = item & 31;
        int gb = (p >> 3) * 16 + (q >> 1);
        int pk = p & 7;
        int comp = (pk >> 2) & 1;
        const float* a = (const float*)&v0[it];
        const float* b = (const float*)&v1[it];
#pragma unroll
        for (int j = 0; j < 4; ++j) {
            int lane = ((((q & 1) << 2) + j) << 2) + (pk & 3);
            Bs[gb * 66 + lane * 2 + comp] = h2u(a[j], b[j]);
        }
    }
}

// ---- raw weight-image chunk copy (528 uint4 = 2112 words)
__device__ __forceinline__ void ldg_W(uint4 v[3], const uint4* __restrict__ W, int tid)
{
    v[0] = W[tid];
    v[1] = W[tid + 256];
    v[2] = (tid < 16) ? W[tid + 512] : make_uint4(0u, 0u, 0u, 0u);
}

__device__ __forceinline__ void sts_W(unsigned* __restrict__ Bs, const uint4 v[3], int tid)
{
    *(uint4*)(Bs + 4 * tid)         = v[0];
    *(uint4*)(Bs + 4 * (tid + 256)) = v[1];
    if (tid < 16) *(uint4*)(Bs + 4 * (tid + 512)) = v[2];
}

// build fragment-major fp16 weight images: block = l*8 + stage*4 + chunk
__global__ void convert_w_kernel(const float* __restrict__ W1,
                                 const float* __restrict__ W2all,
                                 unsigned* __restrict__ wfrag)
{
    int b = blockIdx.x;
    int l = b >> 3, stage = (b >> 2) & 1, kc = b & 3;
    const float* W = stage ? (W2all + (size_t)l * HD * HD)
                           : (W1 + (size_t)l * 3 * HD * HD);
    unsigned* dst = wfrag + ((size_t)l * 2 + stage) * WSTAGE + kc * WCHUNK;
    float4 v0[2], v1[2];
    ldg_Bh(v0, v1, W, HD, kc * 32, 0, threadIdx.x);
    sts_Bh(dst, v0, v1, threadIdx.x);
}

// one 32-k chunk (2 ktile16) of warp-tile 64x32 fp16 mma
__device__ __forceinline__ void mma_chunk_h(float acc[4][4][4],
                                            const unsigned* __restrict__ Af, int mg0, int gs, int gk0,
                                            const unsigned* __restrict__ Bs, int ng0, int lane)
{
#pragma unroll
    for (int kt = 0; kt < 2; ++kt) {
        uint4 a[4]; uint2 b[4];
#pragma unroll
        for (int mi = 0; mi < 4; ++mi)
            a[mi] = *(const uint4*)&Af[((mg0 + mi) * gs + gk0 + kt) * 132 + lane * 4];
#pragma unroll
        for (int ni = 0; ni < 4; ++ni)
            b[ni] = *(const uint2*)&Bs[((kt << 4) + ng0 + ni) * 66 + lane * 2];
#pragma unroll
        for (int mi = 0; mi < 4; ++mi)
#pragma unroll
            for (int ni = 0; ni < 4; ++ni)
                mma_f16(acc[mi][ni], a[mi].x, a[mi].y, a[mi].z, a[mi].w,
                        b[ni].x, b[ni].y);
    }
}

#define ACC_ZERO(acc) \
    _Pragma("unroll") for (int mi = 0; mi < 4; ++mi) \
    _Pragma("unroll") for (int ni = 0; ni < 4; ++ni) \
    _Pragma("unroll") for (int j = 0; j < 4; ++j) acc[mi][ni][j] = 0.f;

// ---------------- fused edge MLP (2 stages fp16; W3 hoisted) ----------------
#define WB_WORDS WSTAGE            // 8448 = W1a resident; == Cs (64 groups * 132)
#define CHUNK_WORDS 2112           // streamed chunk
#define EDGE_SMEM ((WB_WORDS + 2 * CHUNK_WORDS + 256) * 4)
#define GEMM_SMEM ((4 * CHUNK_WORDS) * 4)
#define GEMMLN_SMEM ((4 * CHUNK_WORDS + 2 * 128 * 4) * 4)

__global__ __launch_bounds__(256, 2)
void edge_mlp_tc(const float* __restrict__ hE,
                 const int* __restrict__ esrc,
                 const int* __restrict__ edst,
                 const float* __restrict__ XVs,
                 const float* __restrict__ XVd,
                 const unsigned* __restrict__ wfrag,   // [W1a image | W2 image]
                 const float* __restrict__ b1, const float* __restrict__ b2,
                 float* __restrict__ agg, int E)
{
    extern __shared__ unsigned smem_u[];
    unsigned* WB = smem_u;                  // W1a resident; later Cs
    unsigned* Asb[2] = { WB + WB_WORDS, WB + WB_WORDS + CHUNK_WORDS };
    int* s_src = (int*)(WB + WB_WORDS + 2 * CHUNK_WORDS);
    int* s_dst = s_src + 128;

    const int tid = threadIdx.x;
    const int lane = tid & 31;
    const int wid = tid >> 5;
    const int mrow0 = (wid >> 2) * 64;
    const int ncol0 = (wid & 3) * 32;
    const int mg0 = mrow0 >> 4;
    const int ng0 = ncol0 >> 3;
    const int lq = lane >> 2;
    const int lr = lane & 3;
    const int e0 = blockIdx.x * 128;

    if (tid < 128) {
        int e = e0 + tid;
        s_src[tid] = (e < E) ? esrc[e] : -1;
        s_dst[tid] = (e < E) ? edst[e] : -1;
    }

    float4 va[4];
    uint4 vw[3];
    float acc[4][4][4];

    // ================= stage 1: hE @ W1a (W resident, A ping-pong) ==========
    ACC_ZERO(acc);
    {   // raw copy W1a image (2112 uint4)
        const uint4* src = (const uint4*)wfrag;
        for (int i = tid; i < 2112; i += 256)
            *(uint4*)(WB + 4 * i) = src[i];
    }
    ldg_A(va, hE, HD, e0, E, 0, tid);
    sts_A_h(Asb[0], va, tid);
    __syncthreads();

#pragma unroll
    for (int kc = 0; kc < 4; ++kc) {
        if (kc < 3) ldg_A(va, hE, HD, e0, E, (kc + 1) * 32, tid);
        mma_chunk_h(acc, Asb[kc & 1], mg0, 2, 0, WB + kc * CHUNK_WORDS, ng0, lane);
        if (kc < 3) sts_A_h(Asb[(kc + 1) & 1], va, tid);
        __syncthreads();
    }

    unsigned* Cs = WB;   // alias — all W1a reads are done
    const uint4* W2img = (const uint4*)(wfrag + WSTAGE);

    // prefetch W2 chunk 0 (lands while epilogue runs)
    ldg_W(vw, W2img, tid);

    // epilogue 1: + b1 + XVs[src] + XVd[dst], relu, half2 -> Cs (fp16 A-frag order)
#pragma unroll
    for (int ni = 0; ni < 4; ++ni) {
        int cb = ncol0 + ni * 8 + 2 * lr;
        int pk = cb >> 1;
        int gk = pk >> 3;
        int pkl = pk & 7;
        float b10 = b1[cb], b11 = b1[cb + 1];
#pragma unroll
        for (int mi = 0; mi < 4; ++mi) {
#pragma unroll
            for (int h = 0; h < 2; ++h) {
                int r = mrow0 + mi * 16 + lq + h * 8;
                int ns = s_src[r], nd = s_dst[r];
                float w0 = 0.f, w1 = 0.f;
                if (ns >= 0) {
                    float2 xs = *(const float2*)(XVs + (size_t)ns * HD + cb);
                    float2 xd = *(const float2*)(XVd + (size_t)nd * HD + cb);
                    w0 = acc[mi][ni][h * 2 + 0] + b10 + xs.x + xd.x;
                    w1 = acc[mi][ni][h * 2 + 1] + b11 + xs.y + xd.y;
                }
                int idx = ((mg0 + mi) * 8 + gk) * 132
                        + (((lq << 2) | (pkl & 3)) << 2) + h + (((pkl >> 2) & 1) << 1);
                Cs[idx] = h2u(fmaxf(w0, 0.f), fmaxf(w1, 0.f));
            }
        }
    }
    sts_W(Asb[0], vw, tid);
    __syncthreads();

    // ================= stage 2: C1 @ W2 (W ping-pong, raw copies) ===========
    ACC_ZERO(acc);
#pragma unroll
    for (int kc = 0; kc < 4; ++kc) {
        if (kc < 3) ldg_W(vw, W2img + (kc + 1) * 528, tid);
        mma_chunk_h(acc, Cs, mg0, 8, kc * 2, Asb[kc & 1], ng0, lane);
        if (kc < 3) sts_W(Asb[(kc + 1) & 1], vw, tid);
        __syncthreads();
    }

    // epilogue 2 (final): relu(acc + b2) as half2 row-major (pitch 66) for scatter
#pragma unroll
    for (int ni = 0; ni < 4; ++ni) {
        int cb = ncol0 + ni * 8 + 2 * lr;
        int pk = cb >> 1;
        float b20 = b2[cb], b21 = b2[cb + 1];
#pragma unroll
        for (int mi = 0; mi < 4; ++mi) {
#pragma unroll
            for (int h = 0; h < 2; ++h) {
                int r = mrow0 + mi * 16 + lq + h * 8;
                Cs[r * 66 + pk] = h2u(fmaxf(acc[mi][ni][h * 2 + 0] + b20, 0.f),
                                      fmaxf(acc[mi][ni][h * 2 + 1] + b21, 0.f));
            }
        }
    }
    __syncthreads();

    // cooperative vector scatter of relu(C2): 128 rows x 32 float4
    for (int item = tid; item < 128 * 32; item += 256) {
        int row = item >> 5, q = item & 31;
        int node = s_src[row];
        if (node >= 0) {
            unsigned w0 = Cs[row * 66 + q * 2];
            unsigned w1 = Cs[row * 66 + q * 2 + 1];
            __half2 h0 = *(__half2*)&w0;
            __half2 h1 = *(__half2*)&w1;
            float* p = agg + (size_t)node * HD + q * 4;
            asm volatile("red.global.add.v4.f32 [%0], {%1,%2,%3,%4};"
                         :: "l"(p),
                            "f"(__low2float(h0)), "f"(__high2float(h0)),
                            "f"(__low2float(h1)), "f"(__high2float(h1))
                         : "memory");
        }
    }
}

// ---------------- fp16 node GEMM (128x128 tile, double-buffered) ------------
// epi 0: relu(A@B + bias); epi 2: A@B (no bias)
// blockIdx.z selects (B,C) or (B2,C2). zbuf (if set, z==0 only): zero rows of it.
__global__ __launch_bounds__(256, 2)
void gemm_tc(const float* __restrict__ A, const float* __restrict__ B,
             const float* __restrict__ B2,
             const float* __restrict__ bias,
             float* __restrict__ C, float* __restrict__ C2,
             float* __restrict__ zbuf,
             int M, int N, int K, int epi)
{
    extern __shared__ unsigned smem_u[];
    unsigned* Asb[2] = { smem_u, smem_u + CHUNK_WORDS };
    unsigned* Bsb[2] = { smem_u + 2 * CHUNK_WORDS, smem_u + 3 * CHUNK_WORDS };

    const int tid = threadIdx.x;
    const int lane = tid & 31;
    const int wid = tid >> 5;
    const int mrow0 = (wid >> 2) * 64;
    const int ncol0 = (wid & 3) * 32;
    const int mg0 = mrow0 >> 4;
    const int ng0 = ncol0 >> 3;
    const int lq = lane >> 2;
    const int lr = lane & 3;
    const int m0 = blockIdx.y * 128, n0 = blockIdx.x * 128;
    if (blockIdx.z) { B = B2; C = C2; zbuf = nullptr; }

    // fused zero of the scatter accumulator (rows of this CTA's tile)
    if (zbuf) {
        const float4 z4 = make_float4(0.f, 0.f, 0.f, 0.f);
        for (int item = tid; item < 128 * 32; item += 256) {
            int row = m0 + (item >> 5);
            if (row < M)
                *(float4*)(zbuf + (size_t)row * HD + (item & 31) * 4) = z4;
        }
    }

    float4 va[4];
    float4 v0[2], v1[2];
    float acc[4][4][4];
    ACC_ZERO(acc);

    const int nkc = K / 32;
    ldg_A(va, A, K, m0, M, 0, tid);
    ldg_Bh(v0, v1, B, N, 0, n0, tid);
    sts_A_h(Asb[0], va, tid);
    sts_Bh(Bsb[0], v0, v1, tid);
    __syncthreads();

    for (int kc = 0; kc < nkc; ++kc) {
        if (kc + 1 < nkc) {
            ldg_A(va, A, K, m0, M, (kc + 1) * 32, tid);
            ldg_Bh(v0, v1, B, N, (kc + 1) * 32, n0, tid);
        }
        mma_chunk_h(acc, Asb[kc & 1], mg0, 2, 0, Bsb[kc & 1], ng0, lane);
        if (kc + 1 < nkc) {
            sts_A_h(Asb[(kc + 1) & 1], va, tid);
            sts_Bh(Bsb[(kc + 1) & 1], v0, v1, tid);
        }
        __syncthreads();
    }

#pragma unroll
    for (int ni = 0; ni < 4; ++ni) {
        int c = n0 + ncol0 + ni * 8 + 2 * lr;
        float bb0 = (epi == 2) ? 0.f : bias[c];
        float bb1 = (epi == 2) ? 0.f : bias[c + 1];
#pragma unroll
        for (int mi = 0; mi < 4; ++mi) {
#pragma unroll
            for (int h = 0; h < 2; ++h) {
                int r = m0 + mrow0 + mi * 16 + lq + h * 8;
                if (r < M) {
                    float w0 = acc[mi][ni][h * 2 + 0] + bb0;
                    float w1 = acc[mi][ni][h * 2 + 1] + bb1;
                    if (epi == 0) { w0 = fmaxf(w0, 0.f); w1 = fmaxf(w1, 0.f); }
                    C[(size_t)r * N + c]     = w0;
                    C[(size_t)r * N + c + 1] = w1;
                }
            }
        }
    }
}

// ---------------- fused GEMM + residual + LayerNorm (N = 128 fixed) ---------
// out = LN(res + (A@B)*inv_deg + bias), register-resident LN.
__global__ __launch_bounds__(256, 2)
void gemm_ln(const float* __restrict__ A, const float* __restrict__ B,
             const float* __restrict__ bias, const float* __restrict__ res,
             const float* __restrict__ deg,
             const float* __restrict__ lng, const float* __restrict__ lnb,
             float* __restrict__ out, int M, int K)
{
    extern __shared__ unsigned smem_u[];
    unsigned* Asb[2] = { smem_u, smem_u + CHUNK_WORDS };
    unsigned* Bsb[2] = { smem_u + 2 * CHUNK_WORDS, smem_u + 3 * CHUNK_WORDS };
    float* s_sum = (float*)(smem_u + 4 * CHUNK_WORDS);  // [128][4]
    float* s_sqs = s_sum + 128 * 4;                     // [128][4]

    const int tid = threadIdx.x;
    const int lane = tid & 31;
    const int wid = tid >> 5;
    const int mrow0 = (wid >> 2) * 64;
    const int ncol0 = (wid & 3) * 32;
    const int mg0 = mrow0 >> 4;
    const int ng0 = ncol0 >> 3;
    const int lq = lane >> 2;
    const int lr = lane & 3;
    const int wc = wid & 3;
    const int m0 = blockIdx.y * 128;

    float4 va[4];
    float4 v0[2], v1[2];
    float acc[4][4][4];
    ACC_ZERO(acc);

    const int nkc = K / 32;
    ldg_A(va, A, K, m0, M, 0, tid);
    ldg_Bh(v0, v1, B, HD, 0, 0, tid);
    sts_A_h(Asb[0], va, tid);
    sts_Bh(Bsb[0], v0, v1, tid);
    __syncthreads();

    for (int kc = 0; kc < nkc; ++kc) {
        if (kc + 1 < nkc) {
            ldg_A(va, A, K, m0, M, (kc + 1) * 32, tid);
            ldg_Bh(v0, v1, B, HD, (kc + 1) * 32, 0, tid);
        }
        mma_chunk_h(acc, Asb[kc & 1], mg0, 2, 0, Bsb[kc & 1], ng0, lane);
        if (kc + 1 < nkc) {
            sts_A_h(Asb[(kc + 1) & 1], va, tid);
            sts_Bh(Bsb[(kc + 1) & 1], v0, v1, tid);
        }
        __syncthreads();
    }

    // x = res + acc*inv_deg + bias (in registers); publish per-(row,warp) partials
#pragma unroll
    for (int mi = 0; mi < 4; ++mi) {
#pragma unroll
        for (int h = 0; h < 2; ++h) {
            int r = mrow0 + mi * 16 + lq + h * 8;
            int rg = m0 + r;
            float ps = 0.f, pq = 0.f;
            if (rg < M) {
                float id = deg ? (1.f / fmaxf(deg[rg], 1.f)) : 1.f;
#pragma unroll
                for (int ni = 0; ni < 4; ++ni) {
                    int c = ncol0 + ni * 8 + 2 * lr;
                    float2 rr = *(const float2*)(res + (size_t)rg * HD + c);
                    float x0 = rr.x + acc[mi][ni][h * 2 + 0] * id + bias[c];
                    float x1 = rr.y + acc[mi][ni][h * 2 + 1] * id + bias[c + 1];
                    acc[mi][ni][h * 2 + 0] = x0;
                    acc[mi][ni][h * 2 + 1] = x1;
                    ps += x0 + x1;
                    pq += x0 * x0 + x1 * x1;
                }
            }
            ps += __shfl_xor_sync(0xffffffffu, ps, 1);
            pq += __shfl_xor_sync(0xffffffffu, pq, 1);
            ps += __shfl_xor_sync(0xffffffffu, ps, 2);
            pq += __shfl_xor_sync(0xffffffffu, pq, 2);
            if (lr == 0) {
                s_sum[r * 4 + wc] = ps;
                s_sqs[r * 4 + wc] = pq;
            }
        }
    }
    __syncthreads();

#pragma unroll
    for (int mi = 0; mi < 4; ++mi) {
#pragma unroll
        for (int h = 0; h < 2; ++h) {
            int r = mrow0 + mi * 16 + lq + h * 8;
            int rg = m0 + r;
            if (rg < M) {
                float s = s_sum[r * 4 + 0] + s_sum[r * 4 + 1]
                        + s_sum[r * 4 + 2] + s_sum[r * 4 + 3];
                float q = s_sqs[r * 4 + 0] + s_sqs[r * 4 + 1]
                        + s_sqs[r * 4 + 2] + s_sqs[r * 4 + 3];
                float mu = s * (1.f / HD);
                float var = q * (1.f / HD) - mu * mu;
                float inv = rsqrtf(var + 1e-5f);
#pragma unroll
                for (int ni = 0; ni < 4; ++ni) {
                    int c = ncol0 + ni * 8 + 2 * lr;
                    float2 o;
                    o.x = (acc[mi][ni][h * 2 + 0] - mu) * inv * lng[c]     + lnb[c];
                    o.y = (acc[mi][ni][h * 2 + 1] - mu) * inv * lng[c + 1] + lnb[c + 1];
                    *(float2*)(out + (size_t)rg * HD + c) = o;
                }
            }
        }
    }
}

// ---------------- pooling / heads ------------------------------------------
__global__ void pool_kernel(const float* __restrict__ hV, const int* __restrict__ batch_id,
                            float* __restrict__ pool, float* __restrict__ pcnt, int N)
{
    int i = blockIdx.x * blockDim.x + threadIdx.x;
    if (i < N * HD) {
        int n = i >> 7, c = i & 127;
        atomicAdd(&pool[batch_id[n] * HD + c], hV[i]);
    }
    if (i < N) atomicAdd(&pcnt[batch_id[i]], 1.f);
}

__global__ void head_kernel(const float* __restrict__ pool, const float* __restrict__ pcnt,
                            const float* __restrict__ P1, const float* __restrict__ P2,
                            const float* __restrict__ p2b, float* __restrict__ out)
{
    __shared__ float embs[NB * HD];
    __shared__ float t1[NB * HD];
    int tid = threadIdx.x;
    for (int i = tid; i < NB * HD; i += blockDim.x) {
        int bb = i >> 7;
        embs[i] = pool[i] / fmaxf(pcnt[bb], 1.f);
    }
    __syncthreads();
    for (int i = tid; i < NB * HD; i += blockDim.x) {
        int bb = i >> 7, j = i & 127;
        float s = 0.f;
        for (int k = 0; k < HD; k++) s += embs[bb * HD + k] * P1[k * HD + j];
        t1[i] = fmaxf(s, 0.f);
    }
    __syncthreads();
    for (int i = tid; i < NB * HD; i += blockDim.x) {
        int bb = i >> 7, j = i & 127;
        float s = p2b[j];
        for (int k = 0; k < HD; k++) s += t1[bb * HD + k] * P2[k * HD + j];
        out[i] = s;
    }
}

__global__ void logits_kernel(const float* __restrict__ hV, const int* __restrict__ S,
                              const float* __restrict__ R, const float* __restrict__ rb,
                              float* __restrict__ out, int N)
{
    __shared__ float Rs[HD * NV];
    __shared__ float rbs[NV];
    int tid = threadIdx.x;
    for (int i = tid; i < HD * NV; i += blockDim.x) Rs[i] = R[i];
    if (tid < NV) rbs[tid] = rb[tid];
    __syncthreads();
    int n = blockIdx.x * blockDim.x + tid;
    if (n < N) {
        float a0 = rbs[0], a1 = rbs[1], a2 = rbs[2], a3 = rbs[3];
        const float* h = hV + (size_t)n * HD;
#pragma unroll 8
        for (int k = 0; k < HD; k++) {
            float hv = h[k];
            a0 += hv * Rs[k * NV + 0];
            a1 += hv * Rs[k * NV + 1];
            a2 += hv * Rs[k * NV + 2];
            a3 += hv * Rs[k * NV + 3];
        }
        out[(size_t)n * NV + 0] = a0;
        out[(size_t)n * NV + 1] = a1;
        out[(size_t)n * NV + 2] = a2;
        out[(size_t)n * NV + 3] = a3;
        out[(size_t)N * NV + n] = (float)S[n];
    }
}

// ---------------- launch ----------------------------------------------------
extern "C" void kernel_launch(void* const* d_in, const int* in_sizes, int n_in,
                              void* d_out, int out_size)
{
    const float* h_V  = (const float*)d_in[0];
    const float* h_E  = (const float*)d_in[1];
    const int*   Eidx = (const int*)d_in[2];
    const int*   bid  = (const int*)d_in[3];
    const int*   S    = (const int*)d_in[4];
    const float* W1   = (const float*)d_in[5];
    const float* b1   = (const float*)d_in[6];
    const float* W2   = (const float*)d_in[7];
    const float* b2   = (const float*)d_in[8];
    const float* W3   = (const float*)d_in[9];
    const float* b3   = (const float*)d_in[10];
    const float* ln1g = (const float*)d_in[11];
    const float* ln1b = (const float*)d_in[12];
    const float* Wi   = (const float*)d_in[13];
    const float* bi   = (const float*)d_in[14];
    const float* Wo   = (const float*)d_in[15];
    const float* bo   = (const float*)d_in[16];
    const float* ln2g = (const float*)d_in[17];
    const float* ln2b = (const float*)d_in[18];
    const float* P1   = (const float*)d_in[19];
    const float* P2   = (const float*)d_in[20];
    const float* p2b  = (const float*)d_in[21];
    const float* R    = (const float*)d_in[22];
    const float* rb   = (const float*)d_in[23];

    const int N = in_sizes[0] / HD;
    const int E = in_sizes[2] / 2;
    const int* esrc = Eidx;
    const int* edst = Eidx + E;

    float *p_hV, *p_agg, *p_ffn, *p_xvs, *p_xvd, *p_deg, *p_pool, *p_pcnt;
    void *p_wfrag;
    cudaGetSymbolAddress((void**)&p_hV,   g_hV);
    cudaGetSymbolAddress((void**)&p_agg,  g_agg);
    cudaGetSymbolAddress((void**)&p_ffn,  g_ffn);
    cudaGetSymbolAddress((void**)&p_xvs,  g_xvs);
    cudaGetSymbolAddress((void**)&p_xvd,  g_xvd);
    cudaGetSymbolAddress((void**)&p_deg,  g_deg);
    cudaGetSymbolAddress((void**)&p_pool, g_pool);
    cudaGetSymbolAddress((void**)&p_pcnt, g_pcnt);
    cudaGetSymbolAddress(&p_wfrag, g_wfrag);

    cudaFuncSetAttribute(edge_mlp_tc,
                         cudaFuncAttributeMaxDynamicSharedMemorySize, EDGE_SMEM);
    cudaFuncSetAttribute(gemm_tc,
                         cudaFuncAttributeMaxDynamicSharedMemorySize, GEMM_SMEM);
    cudaFuncSetAttribute(gemm_ln,
                         cudaFuncAttributeMaxDynamicSharedMemorySize, GEMMLN_SMEM);

    copy_kernel<<<(N * HD + 255) / 256, 256>>>(p_hV, h_V, N * HD);

    zero_kernel<<<(N + 255) / 256, 256>>>(p_deg, N);
    deg_kernel<<<(E + 255) / 256, 256>>>(esrc, p_deg, E);

    // one-time fp16 fragment-major weight images (cheap: 48 CTAs)
    convert_w_kernel<<<NL * 8, 256>>>(W1, W2, (unsigned*)p_wfrag);

    const int edge_grid = (E + 127) / 128;
    const int mtiles = (N + 127) / 128;

    for (int l = 0; l < NL; ++l) {
        const float* W1l = W1 + (size_t)l * 3 * HD * HD;
        // fused pre-GEMMs (+ zero agg): XVs = hV @ W1[128:256], XVd = hV @ W1[256:384]
        gemm_tc<<<dim3(1, mtiles, 2), 256, GEMM_SMEM>>>(
            p_hV, W1l + (size_t)HD * HD, W1l + (size_t)2 * HD * HD,
            nullptr, p_xvs, p_xvd, p_agg, N, HD, HD, 2);

        edge_mlp_tc<<<edge_grid, 256, EDGE_SMEM>>>(
            h_E, esrc, edst, p_xvs, p_xvd,
            (const unsigned*)p_wfrag + (size_t)l * 2 * WSTAGE,
            b1 + (size_t)l * HD, b2 + (size_t)l * HD,
            p_agg, E);
        // hV = LN(hV + (agg@W3)/deg + b3)
        gemm_ln<<<dim3(1, mtiles), 256, GEMMLN_SMEM>>>(
            p_agg, W3 + (size_t)l * HD * HD, b3 + (size_t)l * HD,
            p_hV, p_deg,
            ln1g + (size_t)l * HD, ln1b + (size_t)l * HD, p_hV, N, HD);
        // FFN up: relu(hV @ Wi + bi)
        gemm_tc<<<dim3(4, mtiles, 1), 256, GEMM_SMEM>>>(
            p_hV, Wi + (size_t)l * HD * 4 * HD, nullptr,
            bi + (size_t)l * 4 * HD, p_ffn, nullptr, nullptr, N, 4 * HD, HD, 0);
        // hV = LN(hV + ffn@Wo + bo)
        gemm_ln<<<dim3(1, mtiles), 256, GEMMLN_SMEM>>>(
            p_ffn, Wo + (size_t)l * 4 * HD * HD, bo + (size_t)l * HD,
            p_hV, nullptr,
            ln2g + (size_t)l * HD, ln2b + (size_t)l * HD, p_hV, N, 4 * HD);
    }

    zero_kernel<<<(NB * HD + 255) / 256, 256>>>(p_pool, NB * HD);
    zero_kernel<<<1, 32>>>(p_pcnt, NB);
    pool_kernel<<<(N * HD + 255) / 256, 256>>>(p_hV, bid, p_pool, p_pcnt, N);

    float* out = (float*)d_out;
    head_kernel<<<1, 256>>>(p_pool, p_pcnt, P1, P2, p2b,
                            out + (size_t)N * NV + N);
    logits_kernel<<<(N + 255) / 256, 256>>>(p_hV, S, R, rb, out, N);
}

// round 14
// speedup vs baseline: 1.0850x; 1.0699x over previous
#include <cuda_runtime.h>
#include <cuda_fp16.h>
#include <math.h>

#define HD 128
#define NB 16     // batches
#define NV 4      // vocab
#define NL 6      // layers
#define MAXN 20000
#define MAXE 600000

// ---------------- scratch (static device allocs; cudaMalloc is banned) -----
__device__ float g_hV[MAXN * HD];
__device__ float g_agg[MAXN * HD];
__device__ float g_xvs[MAXN * HD];
__device__ float g_xvd[MAXN * HD];
__device__ float g_deg[MAXN];
__device__ float g_pool[NB * HD];
__device__ float g_pcnt[NB];

// ---------------- tiny utility kernels -------------------------------------
__global__ void zero_kernel(float* __restrict__ p, int n) {
    int i = blockIdx.x * blockDim.x + threadIdx.x;
    if (i < n) p[i] = 0.f;
}

__global__ void copy_kernel(float* __restrict__ dst, const float* __restrict__ src, int n) {
    int i = blockIdx.x * blockDim.x + threadIdx.x;
    if (i < n) dst[i] = src[i];
}

__global__ void deg_kernel(const int* __restrict__ src, float* __restrict__ deg, int E) {
    int i = blockIdx.x * blockDim.x + threadIdx.x;
    if (i < E) atomicAdd(&deg[src[i]], 1.f);
}

// ---------------- fp16 + fragment-major helpers -----------------------------
__device__ __forceinline__ unsigned h2u(float lo, float hi) {
    __half2 h = __floats2half2_rn(lo, hi);
    return *(unsigned*)&h;
}

__device__ __forceinline__ void mma_f16(float c[4],
                                        unsigned a0, unsigned a1, unsigned a2, unsigned a3,
                                        unsigned b0, unsigned b1) {
    asm volatile(
        "mma.sync.aligned.m16n8k16.row.col.f32.f16.f16.f32 "
        "{%0,%1,%2,%3}, {%4,%5,%6,%7}, {%8,%9}, {%0,%1,%2,%3};"
        : "+f"(c[0]), "+f"(c[1]), "+f"(c[2]), "+f"(c[3])
        : "r"(a0), "r"(a1), "r"(a2), "r"(a3), "r"(b0), "r"(b1));
}

// ---- A chunk (128 rows x 32 k f32) -> 16 groups of half2 words, pitch 132
__device__ __forceinline__ void ldg_A(float4 v[4], const float* __restrict__ A,
                                      size_t lda, int row0, int M, int kglob0, int tid)
{
#pragma unroll
    for (int it = 0; it < 4; ++it) {
        int item = tid + it * 256;
        int row = item >> 3, q = item & 7;
        v[it] = make_float4(0.f, 0.f, 0.f, 0.f);
        if (row0 + row < M)
            v[it] = *(const float4*)(A + (size_t)(row0 + row) * lda + kglob0 + q * 4);
    }
}

__device__ __forceinline__ void sts_A_h(unsigned* __restrict__ As, const float4 v[4], int tid)
{
#pragma unroll
    for (int it = 0; it < 4; ++it) {
        int item = tid + it * 256;
        int row = item >> 3, q = item & 7;
        int g = ((row >> 4) << 1) + (q >> 2);
        int pk0 = (q & 3) * 2;
        int pk1 = pk0 + 1;
        int off0 = ((((row & 7) << 2) | (pk0 & 3)) << 2) + ((row >> 3) & 1) + (((pk0 >> 2) & 1) << 1);
        int off1 = ((((row & 7) << 2) | (pk1 & 3)) << 2) + ((row >> 3) & 1) + (((pk1 >> 2) & 1) << 1);
        As[g * 132 + off0] = h2u(v[it].x, v[it].y);
        As[g * 132 + off1] = h2u(v[it].z, v[it].w);
    }
}

// ---- B chunk (32 k x 128 n f32) -> 32 groups, pitch 66
__device__ __forceinline__ void ldg_Bh(float4 v0[2], float4 v1[2],
                                       const float* __restrict__ B, size_t ldb,
                                       int kglob0, int n0, int tid)
{
#pragma unroll
    for (int it = 0; it < 2; ++it) {
        int item = tid + it * 256;
        int p = item >> 5, q = item & 31;
        const float* base = B + (size_t)(kglob0 + 2 * p) * ldb + n0 + q * 4;
        v0[it] = *(const float4*)base;
        v1[it] = *(const float4*)(base + ldb);
    }
}

__device__ __forceinline__ void sts_Bh(unsigned* __restrict__ Bs,
                                       const float4 v0[2], const float4 v1[2], int tid)
{
#pragma unroll
    for (int it = 0; it < 2; ++it) {
        int item = tid + it * 256;
        int p = item >> 5, q = item & 31;
        int gb = (p >> 3) * 16 + (q >> 1);
        int pk = p & 7;
        int comp = (pk >> 2) & 1;
        const float* a = (const float*)&v0[it];
        const float* b = (const float*)&v1[it];
#pragma unroll
        for (int j = 0; j < 4; ++j) {
            int lane = ((((q & 1) << 2) + j) << 2) + (pk & 3);
            Bs[gb * 66 + lane * 2 + comp] = h2u(a[j], b[j]);
        }
    }
}

// one 32-k chunk (2 ktile16) of warp-tile 64x32 fp16 mma (4 mtiles)
__device__ __forceinline__ void mma_chunk_h(float acc[4][4][4],
                                            const unsigned* __restrict__ Af, int mg0, int gs, int gk0,
                                            const unsigned* __restrict__ Bs, int ng0, int lane)
{
#pragma unroll
    for (int kt = 0; kt < 2; ++kt) {
        uint4 a[4]; uint2 b[4];
#pragma unroll
        for (int mi = 0; mi < 4; ++mi)
            a[mi] = *(const uint4*)&Af[((mg0 + mi) * gs + gk0 + kt) * 132 + lane * 4];
#pragma unroll
        for (int ni = 0; ni < 4; ++ni)
            b[ni] = *(const uint2*)&Bs[((kt << 4) + ng0 + ni) * 66 + lane * 2];
#pragma unroll
        for (int mi = 0; mi < 4; ++mi)
#pragma unroll
            for (int ni = 0; ni < 4; ++ni)
                mma_f16(acc[mi][ni], a[mi].x, a[mi].y, a[mi].z, a[mi].w,
                        b[ni].x, b[ni].y);
    }
}

// same but 2 mtiles (warp tile 32x32) for the 64-row FFN kernel
__device__ __forceinline__ void mma_chunk_h2(float acc[2][4][4],
                                             const unsigned* __restrict__ Af, int mg0, int gs, int gk0,
                                             const unsigned* __restrict__ Bs, int ng0, int lane)
{
#pragma unroll
    for (int kt = 0; kt < 2; ++kt) {
        uint4 a[2]; uint2 b[4];
#pragma unroll
        for (int mi = 0; mi < 2; ++mi)
            a[mi] = *(const uint4*)&Af[((mg0 + mi) * gs + gk0 + kt) * 132 + lane * 4];
#pragma unroll
        for (int ni = 0; ni < 4; ++ni)
            b[ni] = *(const uint2*)&Bs[((kt << 4) + ng0 + ni) * 66 + lane * 2];
#pragma unroll
        for (int mi = 0; mi < 2; ++mi)
#pragma unroll
            for (int ni = 0; ni < 4; ++ni)
                mma_f16(acc[mi][ni], a[mi].x, a[mi].y, a[mi].z, a[mi].w,
                        b[ni].x, b[ni].y);
    }
}

#define ACC_ZERO(acc) \
    _Pragma("unroll") for (int mi = 0; mi < 4; ++mi) \
    _Pragma("unroll") for (int ni = 0; ni < 4; ++ni) \
    _Pragma("unroll") for (int j = 0; j < 4; ++j) acc[mi][ni][j] = 0.f;

#define ACC_ZERO2(acc) \
    _Pragma("unroll") for (int mi = 0; mi < 2; ++mi) \
    _Pragma("unroll") for (int ni = 0; ni < 4; ++ni) \
    _Pragma("unroll") for (int j = 0; j < 4; ++j) acc[mi][ni][j] = 0.f;

// ---------------- fused edge MLP (2 stages fp16; W3 hoisted) ----------------
#define WB_WORDS (4 * 32 * 66)     // 8448 = W1a resident; == Cs (64 groups * 132)
#define CHUNK_WORDS 2112           // streamed chunk
#define EDGE_SMEM ((WB_WORDS + 2 * CHUNK_WORDS + 256) * 4)
#define GEMM_SMEM ((4 * CHUNK_WORDS) * 4)
#define GEMMLN_SMEM ((4 * CHUNK_WORDS + 2 * 128 * 4) * 4)
// ffn_ln: hVt frags 4224 + hidden 16896 + 2 B-chunks 4224 + LN partials 512
#define FFN_SMEM ((4224 + 16896 + 2 * CHUNK_WORDS + 2 * 64 * 4) * 4)

__global__ __launch_bounds__(256, 2)
void edge_mlp_tc(const float* __restrict__ hE,
                 const int* __restrict__ esrc,
                 const int* __restrict__ edst,
                 const float* __restrict__ XVs,
                 const float* __restrict__ XVd,
                 const float* __restrict__ W1a, const float* __restrict__ b1,
                 const float* __restrict__ W2,  const float* __restrict__ b2,
                 float* __restrict__ agg, int E)
{
    extern __shared__ unsigned smem_u[];
    unsigned* WB = smem_u;                  // W1a resident; later Cs
    unsigned* Asb[2] = { WB + WB_WORDS, WB + WB_WORDS + CHUNK_WORDS };
    int* s_src = (int*)(WB + WB_WORDS + 2 * CHUNK_WORDS);
    int* s_dst = s_src + 128;

    const int tid = threadIdx.x;
    const int lane = tid & 31;
    const int wid = tid >> 5;
    const int mrow0 = (wid >> 2) * 64;
    const int ncol0 = (wid & 3) * 32;
    const int mg0 = mrow0 >> 4;
    const int ng0 = ncol0 >> 3;
    const int lq = lane >> 2;
    const int lr = lane & 3;
    const int e0 = blockIdx.x * 128;

    if (tid < 128) {
        int e = e0 + tid;
        s_src[tid] = (e < E) ? esrc[e] : -1;
        s_dst[tid] = (e < E) ? edst[e] : -1;
    }

    float4 va[4];
    float4 v0[2], v1[2];
    float acc[4][4][4];

    // ================= stage 1: hE @ W1a (W resident, A ping-pong) ==========
    ACC_ZERO(acc);
#pragma unroll
    for (int c = 0; c < 4; ++c) {
        ldg_Bh(v0, v1, W1a, HD, c * 32, 0, tid);
        sts_Bh(WB + c * CHUNK_WORDS, v0, v1, tid);
    }
    ldg_A(va, hE, HD, e0, E, 0, tid);
    sts_A_h(Asb[0], va, tid);
    __syncthreads();

#pragma unroll
    for (int kc = 0; kc < 4; ++kc) {
        if (kc < 3) ldg_A(va, hE, HD, e0, E, (kc + 1) * 32, tid);
        mma_chunk_h(acc, Asb[kc & 1], mg0, 2, 0, WB + kc * CHUNK_WORDS, ng0, lane);
        if (kc < 3) sts_A_h(Asb[(kc + 1) & 1], va, tid);
        __syncthreads();
    }

    unsigned* Cs = WB;   // alias — all W1a reads are done

    // prefetch W2 chunk 0 (lands while epilogue runs)
    ldg_Bh(v0, v1, W2, HD, 0, 0, tid);

    // epilogue 1: + b1 + XVs[src] + XVd[dst], relu, half2 -> Cs (fp16 A-frag order)
#pragma unroll
    for (int ni = 0; ni < 4; ++ni) {
        int cb = ncol0 + ni * 8 + 2 * lr;
        int pk = cb >> 1;
        int gk = pk >> 3;
        int pkl = pk & 7;
        float b10 = b1[cb], b11 = b1[cb + 1];
#pragma unroll
        for (int mi = 0; mi < 4; ++mi) {
#pragma unroll
            for (int h = 0; h < 2; ++h) {
                int r = mrow0 + mi * 16 + lq + h * 8;
                int ns = s_src[r], nd = s_dst[r];
                float w0 = 0.f, w1 = 0.f;
                if (ns >= 0) {
                    float2 xs = *(const float2*)(XVs + (size_t)ns * HD + cb);
                    float2 xd = *(const float2*)(XVd + (size_t)nd * HD + cb);
                    w0 = acc[mi][ni][h * 2 + 0] + b10 + xs.x + xd.x;
                    w1 = acc[mi][ni][h * 2 + 1] + b11 + xs.y + xd.y;
                }
                int idx = ((mg0 + mi) * 8 + gk) * 132
                        + (((lq << 2) | (pkl & 3)) << 2) + h + (((pkl >> 2) & 1) << 1);
                Cs[idx] = h2u(fmaxf(w0, 0.f), fmaxf(w1, 0.f));
            }
        }
    }
    sts_Bh(Asb[0], v0, v1, tid);
    __syncthreads();

    // ================= stage 2: C1 @ W2 (W ping-pong) =======================
    ACC_ZERO(acc);
#pragma unroll
    for (int kc = 0; kc < 4; ++kc) {
        if (kc < 3) ldg_Bh(v0, v1, W2, HD, (kc + 1) * 32, 0, tid);
        mma_chunk_h(acc, Cs, mg0, 8, kc * 2, Asb[kc & 1], ng0, lane);
        if (kc < 3) sts_Bh(Asb[(kc + 1) & 1], v0, v1, tid);
        __syncthreads();
    }

    // epilogue 2 (final): relu(acc + b2) as half2 row-major (pitch 66) for scatter
#pragma unroll
    for (int ni = 0; ni < 4; ++ni) {
        int cb = ncol0 + ni * 8 + 2 * lr;
        int pk = cb >> 1;
        float b20 = b2[cb], b21 = b2[cb + 1];
#pragma unroll
        for (int mi = 0; mi < 4; ++mi) {
#pragma unroll
            for (int h = 0; h < 2; ++h) {
                int r = mrow0 + mi * 16 + lq + h * 8;
                Cs[r * 66 + pk] = h2u(fmaxf(acc[mi][ni][h * 2 + 0] + b20, 0.f),
                                      fmaxf(acc[mi][ni][h * 2 + 1] + b21, 0.f));
            }
        }
    }
    __syncthreads();

    // cooperative vector scatter of relu(C2): 128 rows x 32 float4
    for (int item = tid; item < 128 * 32; item += 256) {
        int row = item >> 5, q = item & 31;
        int node = s_src[row];
        if (node >= 0) {
            unsigned w0 = Cs[row * 66 + q * 2];
            unsigned w1 = Cs[row * 66 + q * 2 + 1];
            __half2 h0 = *(__half2*)&w0;
            __half2 h1 = *(__half2*)&w1;
            float* p = agg + (size_t)node * HD + q * 4;
            asm volatile("red.global.add.v4.f32 [%0], {%1,%2,%3,%4};"
                         :: "l"(p),
                            "f"(__low2float(h0)), "f"(__high2float(h0)),
                            "f"(__low2float(h1)), "f"(__high2float(h1))
                         : "memory");
        }
    }
}

// ---------------- fp16 node GEMM (128x128 tile, double-buffered) ------------
// epi 2: A@B (no bias). blockIdx.z selects (B,C)/(B2,C2); zbuf zeroed on z==0.
__global__ __launch_bounds__(256, 2)
void gemm_tc(const float* __restrict__ A, const float* __restrict__ B,
             const float* __restrict__ B2,
             float* __restrict__ C, float* __restrict__ C2,
             float* __restrict__ zbuf,
             int M, int N, int K)
{
    extern __shared__ unsigned smem_u[];
    unsigned* Asb[2] = { smem_u, smem_u + CHUNK_WORDS };
    unsigned* Bsb[2] = { smem_u + 2 * CHUNK_WORDS, smem_u + 3 * CHUNK_WORDS };

    const int tid = threadIdx.x;
    const int lane = tid & 31;
    const int wid = tid >> 5;
    const int mrow0 = (wid >> 2) * 64;
    const int ncol0 = (wid & 3) * 32;
    const int mg0 = mrow0 >> 4;
    const int ng0 = ncol0 >> 3;
    const int lq = lane >> 2;
    const int lr = lane & 3;
    const int m0 = blockIdx.y * 128, n0 = blockIdx.x * 128;
    if (blockIdx.z) { B = B2; C = C2; zbuf = nullptr; }

    if (zbuf) {
        const float4 z4 = make_float4(0.f, 0.f, 0.f, 0.f);
        for (int item = tid; item < 128 * 32; item += 256) {
            int row = m0 + (item >> 5);
            if (row < M)
                *(float4*)(zbuf + (size_t)row * HD + (item & 31) * 4) = z4;
        }
    }

    float4 va[4];
    float4 v0[2], v1[2];
    float acc[4][4][4];
    ACC_ZERO(acc);

    const int nkc = K / 32;
    ldg_A(va, A, K, m0, M, 0, tid);
    ldg_Bh(v0, v1, B, N, 0, n0, tid);
    sts_A_h(Asb[0], va, tid);
    sts_Bh(Bsb[0], v0, v1, tid);
    __syncthreads();

    for (int kc = 0; kc < nkc; ++kc) {
        if (kc + 1 < nkc) {
            ldg_A(va, A, K, m0, M, (kc + 1) * 32, tid);
            ldg_Bh(v0, v1, B, N, (kc + 1) * 32, n0, tid);
        }
        mma_chunk_h(acc, Asb[kc & 1], mg0, 2, 0, Bsb[kc & 1], ng0, lane);
        if (kc + 1 < nkc) {
            sts_A_h(Asb[(kc + 1) & 1], va, tid);
            sts_Bh(Bsb[(kc + 1) & 1], v0, v1, tid);
        }
        __syncthreads();
    }

#pragma unroll
    for (int ni = 0; ni < 4; ++ni) {
        int c = n0 + ncol0 + ni * 8 + 2 * lr;
#pragma unroll
        for (int mi = 0; mi < 4; ++mi) {
#pragma unroll
            for (int h = 0; h < 2; ++h) {
                int r = m0 + mrow0 + mi * 16 + lq + h * 8;
                if (r < M) {
                    C[(size_t)r * N + c]     = acc[mi][ni][h * 2 + 0];
                    C[(size_t)r * N + c + 1] = acc[mi][ni][h * 2 + 1];
                }
            }
        }
    }
}

// ---------------- fused GEMM + residual + LayerNorm (N = 128 fixed) ---------
// out = LN(res + (A@B)*inv_deg + bias), register-resident LN.
__global__ __launch_bounds__(256, 2)
void gemm_ln(const float* __restrict__ A, const float* __restrict__ B,
             const float* __restrict__ bias, const float* __restrict__ res,
             const float* __restrict__ deg,
             const float* __restrict__ lng, const float* __restrict__ lnb,
             float* __restrict__ out, int M, int K)
{
    extern __shared__ unsigned smem_u[];
    unsigned* Asb[2] = { smem_u, smem_u + CHUNK_WORDS };
    unsigned* Bsb[2] = { smem_u + 2 * CHUNK_WORDS, smem_u + 3 * CHUNK_WORDS };
    float* s_sum = (float*)(smem_u + 4 * CHUNK_WORDS);  // [128][4]
    float* s_sqs = s_sum + 128 * 4;                     // [128][4]

    const int tid = threadIdx.x;
    const int lane = tid & 31;
    const int wid = tid >> 5;
    const int mrow0 = (wid >> 2) * 64;
    const int ncol0 = (wid & 3) * 32;
    const int mg0 = mrow0 >> 4;
    const int ng0 = ncol0 >> 3;
    const int lq = lane >> 2;
    const int lr = lane & 3;
    const int wc = wid & 3;
    const int m0 = blockIdx.y * 128;

    float4 va[4];
    float4 v0[2], v1[2];
    float acc[4][4][4];
    ACC_ZERO(acc);

    const int nkc = K / 32;
    ldg_A(va, A, K, m0, M, 0, tid);
    ldg_Bh(v0, v1, B, HD, 0, 0, tid);
    sts_A_h(Asb[0], va, tid);
    sts_Bh(Bsb[0], v0, v1, tid);
    __syncthreads();

    for (int kc = 0; kc < nkc; ++kc) {
        if (kc + 1 < nkc) {
            ldg_A(va, A, K, m0, M, (kc + 1) * 32, tid);
            ldg_Bh(v0, v1, B, HD, (kc + 1) * 32, 0, tid);
        }
        mma_chunk_h(acc, Asb[kc & 1], mg0, 2, 0, Bsb[kc & 1], ng0, lane);
        if (kc + 1 < nkc) {
            sts_A_h(Asb[(kc + 1) & 1], va, tid);
            sts_Bh(Bsb[(kc + 1) & 1], v0, v1, tid);
        }
        __syncthreads();
    }

#pragma unroll
    for (int mi = 0; mi < 4; ++mi) {
#pragma unroll
        for (int h = 0; h < 2; ++h) {
            int r = mrow0 + mi * 16 + lq + h * 8;
            int rg = m0 + r;
            float ps = 0.f, pq = 0.f;
            if (rg < M) {
                float id = deg ? (1.f / fmaxf(deg[rg], 1.f)) : 1.f;
#pragma unroll
                for (int ni = 0; ni < 4; ++ni) {
                    int c = ncol0 + ni * 8 + 2 * lr;
                    float2 rr = *(const float2*)(res + (size_t)rg * HD + c);
                    float x0 = rr.x + acc[mi][ni][h * 2 + 0] * id + bias[c];
                    float x1 = rr.y + acc[mi][ni][h * 2 + 1] * id + bias[c + 1];
                    acc[mi][ni][h * 2 + 0] = x0;
                    acc[mi][ni][h * 2 + 1] = x1;
                    ps += x0 + x1;
                    pq += x0 * x0 + x1 * x1;
                }
            }
            ps += __shfl_xor_sync(0xffffffffu, ps, 1);
            pq += __shfl_xor_sync(0xffffffffu, pq, 1);
            ps += __shfl_xor_sync(0xffffffffu, ps, 2);
            pq += __shfl_xor_sync(0xffffffffu, pq, 2);
            if (lr == 0) {
                s_sum[r * 4 + wc] = ps;
                s_sqs[r * 4 + wc] = pq;
            }
        }
    }
    __syncthreads();

#pragma unroll
    for (int mi = 0; mi < 4; ++mi) {
#pragma unroll
        for (int h = 0; h < 2; ++h) {
            int r = mrow0 + mi * 16 + lq + h * 8;
            int rg = m0 + r;
            if (rg < M) {
                float s = s_sum[r * 4 + 0] + s_sum[r * 4 + 1]
                        + s_sum[r * 4 + 2] + s_sum[r * 4 + 3];
                float q = s_sqs[r * 4 + 0] + s_sqs[r * 4 + 1]
                        + s_sqs[r * 4 + 2] + s_sqs[r * 4 + 3];
                float mu = s * (1.f / HD);
                float var = q * (1.f / HD) - mu * mu;
                float inv = rsqrtf(var + 1e-5f);
#pragma unroll
                for (int ni = 0; ni < 4; ++ni) {
                    int c = ncol0 + ni * 8 + 2 * lr;
                    float2 o;
                    o.x = (acc[mi][ni][h * 2 + 0] - mu) * inv * lng[c]     + lnb[c];
                    o.y = (acc[mi][ni][h * 2 + 1] - mu) * inv * lng[c + 1] + lnb[c + 1];
                    *(float2*)(out + (size_t)rg * HD + c) = o;
                }
            }
        }
    }
}

// ---------------- fused FFN: out = LN(hV + relu(hV@Wi+bi)@Wo + bo) ----------
// One CTA = 64 rows. hidden kept in smem as fp16 A-fragments. 8 warps (2x4),
// warp tile 32x32.
__global__ __launch_bounds__(256, 2)
void ffn_ln(const float* __restrict__ hV,
            const float* __restrict__ Wi, const float* __restrict__ bi,
            const float* __restrict__ Wo, const float* __restrict__ bo,
            const float* __restrict__ lng, const float* __restrict__ lnb,
            float* __restrict__ out, int M)
{
    extern __shared__ unsigned smem_u[];
    unsigned* hVt = smem_u;                       // 4224: 64x128 A-frags (32 groups)
    unsigned* Hid = hVt + 4224;                   // 16896: 64x512 A-frags (128 groups)
    unsigned* Bsb[2] = { Hid + 16896, Hid + 16896 + CHUNK_WORDS };
    float* s_sum = (float*)(Hid + 16896 + 2 * CHUNK_WORDS);  // [64][4]
    float* s_sqs = s_sum + 64 * 4;                           // [64][4]

    const int tid = threadIdx.x;
    const int lane = tid & 31;
    const int wid = tid >> 5;
    const int wr = wid >> 2;           // 0..1: 32-row block
    const int wc = wid & 3;            // 0..3: 32-col block
    const int mrow0 = wr * 32;
    const int ncol0 = wc * 32;
    const int mg0 = mrow0 >> 4;        // 0 or 2
    const int ng0 = ncol0 >> 3;        // 0,4,8,12
    const int lq = lane >> 2;
    const int lr = lane & 3;
    const int m0 = blockIdx.x * 64;

    float4 v0[2], v1[2];

    // ---- load hV tile (64x128) into A-fragments (8 float4 per thread) ----
#pragma unroll
    for (int it = 0; it < 8; ++it) {
        int item = tid + it * 256;
        int row = item >> 5, q = item & 31;          // q: float4 within 128 cols
        float4 v = make_float4(0.f, 0.f, 0.f, 0.f);
        if (m0 + row < M)
            v = *(const float4*)(hV + (size_t)(m0 + row) * HD + q * 4);
        int g = ((row >> 4) << 3) + (q >> 2);        // mtile*8 + ktile16
        int pk0 = (q & 3) * 2, pk1 = pk0 + 1;
        int off0 = ((((row & 7) << 2) | (pk0 & 3)) << 2) + ((row >> 3) & 1) + (((pk0 >> 2) & 1) << 1);
        int off1 = ((((row & 7) << 2) | (pk1 & 3)) << 2) + ((row >> 3) & 1) + (((pk1 >> 2) & 1) << 1);
        hVt[g * 132 + off0] = h2u(v.x, v.y);
        hVt[g * 132 + off1] = h2u(v.z, v.w);
    }
    // prefetch Wi chunk (nb=0, kc=0)
    ldg_Bh(v0, v1, Wi, 4 * HD, 0, 0, tid);
    sts_Bh(Bsb[0], v0, v1, tid);
    __syncthreads();

    // ---- step B: hidden = relu(hVt @ Wi + bi), 4 N-blocks of 128 ----
    int buf = 0;
#pragma unroll
    for (int nb = 0; nb < 4; ++nb) {
        float acc[2][4][4];
        ACC_ZERO2(acc);
#pragma unroll
        for (int kc = 0; kc < 4; ++kc) {
            bool last = (nb == 3) && (kc == 3);
            if (!last) {
                int nxt = nb * 4 + kc + 1;
                ldg_Bh(v0, v1, Wi, 4 * HD, (nxt & 3) * 32, (nxt >> 2) * 128, tid);
            }
            mma_chunk_h2(acc, hVt, mg0, 8, kc * 2, Bsb[buf], ng0, lane);
            if (!last) sts_Bh(Bsb[buf ^ 1], v0, v1, tid);
            __syncthreads();
            buf ^= 1;
        }
        // epilogue: relu(acc + bi) -> Hid fragments (hidden k = nb*128 + col)
#pragma unroll
        for (int ni = 0; ni < 4; ++ni) {
            int cl = ncol0 + ni * 8 + 2 * lr;        // col within block
            int c = nb * 128 + cl;                   // hidden k index
            int pk = c >> 1;
            int gk = pk >> 3;                        // ktile16 (0..31)
            int pkl = pk & 7;
            float bb0 = bi[c], bb1 = bi[c + 1];
#pragma unroll
            for (int mi = 0; mi < 2; ++mi) {
#pragma unroll
                for (int h = 0; h < 2; ++h) {
                    int idx = ((mg0 + mi) * 32 + gk) * 132
                            + (((lq << 2) | (pkl & 3)) << 2) + h + (((pkl >> 2) & 1) << 1);
                    Hid[idx] = h2u(fmaxf(acc[mi][ni][h * 2 + 0] + bb0, 0.f),
                                   fmaxf(acc[mi][ni][h * 2 + 1] + bb1, 0.f));
                }
            }
        }
    }
    // prefetch Wo chunk 0; publish last Hid stores
    ldg_Bh(v0, v1, Wo, HD, 0, 0, tid);
    sts_Bh(Bsb[0], v0, v1, tid);
    __syncthreads();

    // ---- step C: acc2 = Hid @ Wo (K = 512, 16 chunks) ----
    float acc2[2][4][4];
    ACC_ZERO2(acc2);
    for (int kc = 0; kc < 16; ++kc) {
        if (kc < 15) ldg_Bh(v0, v1, Wo, HD, (kc + 1) * 32, 0, tid);
        mma_chunk_h2(acc2, Hid, mg0, 32, kc * 2, Bsb[kc & 1], ng0, lane);
        if (kc < 15) sts_Bh(Bsb[(kc + 1) & 1], v0, v1, tid);
        __syncthreads();
    }

    // ---- epilogue: x = hV + acc2 + bo, register LN, store ----
#pragma unroll
    for (int mi = 0; mi < 2; ++mi) {
#pragma unroll
        for (int h = 0; h < 2; ++h) {
            int r = mrow0 + mi * 16 + lq + h * 8;
            int rg = m0 + r;
            float ps = 0.f, pq = 0.f;
            if (rg < M) {
#pragma unroll
                for (int ni = 0; ni < 4; ++ni) {
                    int c = ncol0 + ni * 8 + 2 * lr;
                    float2 rr = *(const float2*)(hV + (size_t)rg * HD + c);
                    float x0 = rr.x + acc2[mi][ni][h * 2 + 0] + bo[c];
                    float x1 = rr.y + acc2[mi][ni][h * 2 + 1] + bo[c + 1];
                    acc2[mi][ni][h * 2 + 0] = x0;
                    acc2[mi][ni][h * 2 + 1] = x1;
                    ps += x0 + x1;
                    pq += x0 * x0 + x1 * x1;
                }
            }
            ps += __shfl_xor_sync(0xffffffffu, ps, 1);
            pq += __shfl_xor_sync(0xffffffffu, pq, 1);
            ps += __shfl_xor_sync(0xffffffffu, ps, 2);
            pq += __shfl_xor_sync(0xffffffffu, pq, 2);
            if (lr == 0) {
                s_sum[r * 4 + wc] = ps;
                s_sqs[r * 4 + wc] = pq;
            }
        }
    }
    __syncthreads();

#pragma unroll
    for (int mi = 0; mi < 2; ++mi) {
#pragma unroll
        for (int h = 0; h < 2; ++h) {
            int r = mrow0 + mi * 16 + lq + h * 8;
            int rg = m0 + r;
            if (rg < M) {
                float s = s_sum[r * 4 + 0] + s_sum[r * 4 + 1]
                        + s_sum[r * 4 + 2] + s_sum[r * 4 + 3];
                float q = s_sqs[r * 4 + 0] + s_sqs[r * 4 + 1]
                        + s_sqs[r * 4 + 2] + s_sqs[r * 4 + 3];
                float mu = s * (1.f / HD);
                float var = q * (1.f / HD) - mu * mu;
                float inv = rsqrtf(var + 1e-5f);
#pragma unroll
                for (int ni = 0; ni < 4; ++ni) {
                    int c = ncol0 + ni * 8 + 2 * lr;
                    float2 o;
                    o.x = (acc2[mi][ni][h * 2 + 0] - mu) * inv * lng[c]     + lnb[c];
                    o.y = (acc2[mi][ni][h * 2 + 1] - mu) * inv * lng[c + 1] + lnb[c + 1];
                    *(float2*)(out + (size_t)rg * HD + c) = o;
                }
            }
        }
    }
}

// ---------------- pooling / heads ------------------------------------------
__global__ void pool_kernel(const float* __restrict__ hV, const int* __restrict__ batch_id,
                            float* __restrict__ pool, float* __restrict__ pcnt, int N)
{
    int i = blockIdx.x * blockDim.x + threadIdx.x;
    if (i < N * HD) {
        int n = i >> 7, c = i & 127;
        atomicAdd(&pool[batch_id[n] * HD + c], hV[i]);
    }
    if (i < N) atomicAdd(&pcnt[batch_id[i]], 1.f);
}

__global__ void head_kernel(const float* __restrict__ pool, const float* __restrict__ pcnt,
                            const float* __restrict__ P1, const float* __restrict__ P2,
                            const float* __restrict__ p2b, float* __restrict__ out)
{
    __shared__ float embs[NB * HD];
    __shared__ float t1[NB * HD];
    int tid = threadIdx.x;
    for (int i = tid; i < NB * HD; i += blockDim.x) {
        int bb = i >> 7;
        embs[i] = pool[i] / fmaxf(pcnt[bb], 1.f);
    }
    __syncthreads();
    for (int i = tid; i < NB * HD; i += blockDim.x) {
        int bb = i >> 7, j = i & 127;
        float s = 0.f;
        for (int k = 0; k < HD; k++) s += embs[bb * HD + k] * P1[k * HD + j];
        t1[i] = fmaxf(s, 0.f);
    }
    __syncthreads();
    for (int i = tid; i < NB * HD; i += blockDim.x) {
        int bb = i >> 7, j = i & 127;
        float s = p2b[j];
        for (int k = 0; k < HD; k++) s += t1[bb * HD + k] * P2[k * HD + j];
        out[i] = s;
    }
}

__global__ void logits_kernel(const float* __restrict__ hV, const int* __restrict__ S,
                              const float* __restrict__ R, const float* __restrict__ rb,
                              float* __restrict__ out, int N)
{
    __shared__ float Rs[HD * NV];
    __shared__ float rbs[NV];
    int tid = threadIdx.x;
    for (int i = tid; i < HD * NV; i += blockDim.x) Rs[i] = R[i];
    if (tid < NV) rbs[tid] = rb[tid];
    __syncthreads();
    int n = blockIdx.x * blockDim.x + tid;
    if (n < N) {
        float a0 = rbs[0], a1 = rbs[1], a2 = rbs[2], a3 = rbs[3];
        const float* h = hV + (size_t)n * HD;
#pragma unroll 8
        for (int k = 0; k < HD; k++) {
            float hv = h[k];
            a0 += hv * Rs[k * NV + 0];
            a1 += hv * Rs[k * NV + 1];
            a2 += hv * Rs[k * NV + 2];
            a3 += hv * Rs[k * NV + 3];
        }
        out[(size_t)n * NV + 0] = a0;
        out[(size_t)n * NV + 1] = a1;
        out[(size_t)n * NV + 2] = a2;
        out[(size_t)n * NV + 3] = a3;
        out[(size_t)N * NV + n] = (float)S[n];
    }
}

// ---------------- launch ----------------------------------------------------
extern "C" void kernel_launch(void* const* d_in, const int* in_sizes, int n_in,
                              void* d_out, int out_size)
{
    const float* h_V  = (const float*)d_in[0];
    const float* h_E  = (const float*)d_in[1];
    const int*   Eidx = (const int*)d_in[2];
    const int*   bid  = (const int*)d_in[3];
    const int*   S    = (const int*)d_in[4];
    const float* W1   = (const float*)d_in[5];
    const float* b1   = (const float*)d_in[6];
    const float* W2   = (const float*)d_in[7];
    const float* b2   = (const float*)d_in[8];
    const float* W3   = (const float*)d_in[9];
    const float* b3   = (const float*)d_in[10];
    const float* ln1g = (const float*)d_in[11];
    const float* ln1b = (const float*)d_in[12];
    const float* Wi   = (const float*)d_in[13];
    const float* bi   = (const float*)d_in[14];
    const float* Wo   = (const float*)d_in[15];
    const float* bo   = (const float*)d_in[16];
    const float* ln2g = (const float*)d_in[17];
    const float* ln2b = (const float*)d_in[18];
    const float* P1   = (const float*)d_in[19];
    const float* P2   = (const float*)d_in[20];
    const float* p2b  = (const float*)d_in[21];
    const float* R    = (const float*)d_in[22];
    const float* rb   = (const float*)d_in[23];

    const int N = in_sizes[0] / HD;
    const int E = in_sizes[2] / 2;
    const int* esrc = Eidx;
    const int* edst = Eidx + E;

    float *p_hV, *p_agg, *p_xvs, *p_xvd, *p_deg, *p_pool, *p_pcnt;
    cudaGetSymbolAddress((void**)&p_hV,   g_hV);
    cudaGetSymbolAddress((void**)&p_agg,  g_agg);
    cudaGetSymbolAddress((void**)&p_xvs,  g_xvs);
    cudaGetSymbolAddress((void**)&p_xvd,  g_xvd);
    cudaGetSymbolAddress((void**)&p_deg,  g_deg);
    cudaGetSymbolAddress((void**)&p_pool, g_pool);
    cudaGetSymbolAddress((void**)&p_pcnt, g_pcnt);

    cudaFuncSetAttribute(edge_mlp_tc,
                         cudaFuncAttributeMaxDynamicSharedMemorySize, EDGE_SMEM);
    cudaFuncSetAttribute(gemm_tc,
                         cudaFuncAttributeMaxDynamicSharedMemorySize, GEMM_SMEM);
    cudaFuncSetAttribute(gemm_ln,
                         cudaFuncAttributeMaxDynamicSharedMemorySize, GEMMLN_SMEM);
    cudaFuncSetAttribute(ffn_ln,
                         cudaFuncAttributeMaxDynamicSharedMemorySize, FFN_SMEM);

    copy_kernel<<<(N * HD + 255) / 256, 256>>>(p_hV, h_V, N * HD);

    zero_kernel<<<(N + 255) / 256, 256>>>(p_deg, N);
    deg_kernel<<<(E + 255) / 256, 256>>>(esrc, p_deg, E);

    const int edge_grid = (E + 127) / 128;
    const int mtiles = (N + 127) / 128;
    const int mtiles2 = (N + 63) / 64;

    for (int l = 0; l < NL; ++l) {
        const float* W1l = W1 + (size_t)l * 3 * HD * HD;
        // fused pre-GEMMs (+ zero agg): XVs = hV @ W1[128:256], XVd = hV @ W1[256:384]
        gemm_tc<<<dim3(1, mtiles, 2), 256, GEMM_SMEM>>>(
            p_hV, W1l + (size_t)HD * HD, W1l + (size_t)2 * HD * HD,
            p_xvs, p_xvd, p_agg, N, HD, HD);

        edge_mlp_tc<<<edge_grid, 256, EDGE_SMEM>>>(
            h_E, esrc, edst, p_xvs, p_xvd,
            W1l, b1 + (size_t)l * HD,
            W2 + (size_t)l * HD * HD, b2 + (size_t)l * HD,
            p_agg, E);
        // hV = LN(hV + (agg@W3)/deg + b3)
        gemm_ln<<<dim3(1, mtiles), 256, GEMMLN_SMEM>>>(
            p_agg, W3 + (size_t)l * HD * HD, b3 + (size_t)l * HD,
            p_hV, p_deg,
            ln1g + (size_t)l * HD, ln1b + (size_t)l * HD, p_hV, N, HD);
        // hV = LN(hV + relu(hV@Wi+bi)@Wo + bo)   — fully fused FFN
        ffn_ln<<<mtiles2, 256, FFN_SMEM>>>(
            p_hV, Wi + (size_t)l * HD * 4 * HD, bi + (size_t)l * 4 * HD,
            Wo + (size_t)l * 4 * HD * HD, bo + (size_t)l * HD,
            ln2g + (size_t)l * HD, ln2b + (size_t)l * HD, p_hV, N);
    }

    zero_kernel<<<(NB * HD + 255) / 256, 256>>>(p_pool, NB * HD);
    zero_kernel<<<1, 32>>>(p_pcnt, NB);
    pool_kernel<<<(N * HD + 255) / 256, 256>>>(p_hV, bid, p_pool, p_pcnt, N);

    float* out = (float*)d_out;
    head_kernel<<<1, 256>>>(p_pool, p_pcnt, P1, P2, p2b,
                            out + (size_t)N * NV + N);
    logits_kernel<<<(N + 255) / 256, 256>>>(p_hV, S, R, rb, out, N);
}

// round 15
// speedup vs baseline: 1.0961x; 1.0102x over previous
#include <cuda_runtime.h>
#include <cuda_fp16.h>
#include <math.h>

#define HD 128
#define NB 16     // batches
#define NV 4      // vocab
#define NL 6      // layers
#define MAXN 20000
#define MAXE 600000

// ---------------- scratch (static device allocs; cudaMalloc is banned) -----
__device__ float g_hV[MAXN * HD];
__device__ float g_agg[MAXN * HD];
__device__ float g_xvs[MAXN * HD];
__device__ float g_xvd[MAXN * HD];
__device__ float g_deg[MAXN];
__device__ float g_pool[NB * HD];
__device__ float g_pcnt[NB];

// ---------------- tiny utility kernels -------------------------------------
__global__ void zero_kernel(float* __restrict__ p, int n) {
    int i = blockIdx.x * blockDim.x + threadIdx.x;
    if (i < n) p[i] = 0.f;
}

__global__ void copy_kernel(float* __restrict__ dst, const float* __restrict__ src, int n) {
    int i = blockIdx.x * blockDim.x + threadIdx.x;
    if (i < n) dst[i] = src[i];
}

__global__ void deg_kernel(const int* __restrict__ src, float* __restrict__ deg, int E) {
    int i = blockIdx.x * blockDim.x + threadIdx.x;
    if (i < E) atomicAdd(&deg[src[i]], 1.f);
}

// ---------------- fp16 + fragment-major helpers -----------------------------
__device__ __forceinline__ unsigned h2u(float lo, float hi) {
    __half2 h = __floats2half2_rn(lo, hi);
    return *(unsigned*)&h;
}

__device__ __forceinline__ void mma_f16(float c[4],
                                        unsigned a0, unsigned a1, unsigned a2, unsigned a3,
                                        unsigned b0, unsigned b1) {
    asm volatile(
        "mma.sync.aligned.m16n8k16.row.col.f32.f16.f16.f32 "
        "{%0,%1,%2,%3}, {%4,%5,%6,%7}, {%8,%9}, {%0,%1,%2,%3};"
        : "+f"(c[0]), "+f"(c[1]), "+f"(c[2]), "+f"(c[3])
        : "r"(a0), "r"(a1), "r"(a2), "r"(a3), "r"(b0), "r"(b1));
}

// ---- A chunk (128 rows x 32 k f32) -> 16 groups of half2 words, pitch 132
__device__ __forceinline__ void ldg_A(float4 v[4], const float* __restrict__ A,
                                      size_t lda, int row0, int M, int kglob0, int tid)
{
#pragma unroll
    for (int it = 0; it < 4; ++it) {
        int item = tid + it * 256;
        int row = item >> 3, q = item & 7;
        v[it] = make_float4(0.f, 0.f, 0.f, 0.f);
        if (row0 + row < M)
            v[it] = *(const float4*)(A + (size_t)(row0 + row) * lda + kglob0 + q * 4);
    }
}

__device__ __forceinline__ void sts_A_h(unsigned* __restrict__ As, const float4 v[4], int tid)
{
#pragma unroll
    for (int it = 0; it < 4; ++it) {
        int item = tid + it * 256;
        int row = item >> 3, q = item & 7;
        int g = ((row >> 4) << 1) + (q >> 2);
        int pk0 = (q & 3) * 2;
        int pk1 = pk0 + 1;
        int off0 = ((((row & 7) << 2) | (pk0 & 3)) << 2) + ((row >> 3) & 1) + (((pk0 >> 2) & 1) << 1);
        int off1 = ((((row & 7) << 2) | (pk1 & 3)) << 2) + ((row >> 3) & 1) + (((pk1 >> 2) & 1) << 1);
        As[g * 132 + off0] = h2u(v[it].x, v[it].y);
        As[g * 132 + off1] = h2u(v[it].z, v[it].w);
    }
}

// ---- B chunk (32 k x 128 n f32) -> 32 groups, pitch 66
__device__ __forceinline__ void ldg_Bh(float4 v0[2], float4 v1[2],
                                       const float* __restrict__ B, size_t ldb,
                                       int kglob0, int n0, int tid)
{
#pragma unroll
    for (int it = 0; it < 2; ++it) {
        int item = tid + it * 256;
        int p = item >> 5, q = item & 31;
        const float* base = B + (size_t)(kglob0 + 2 * p) * ldb + n0 + q * 4;
        v0[it] = *(const float4*)base;
        v1[it] = *(const float4*)(base + ldb);
    }
}

__device__ __forceinline__ void sts_Bh(unsigned* __restrict__ Bs,
                                       const float4 v0[2], const float4 v1[2], int tid)
{
#pragma unroll
    for (int it = 0; it < 2; ++it) {
        int item = tid + it * 256;
        int p = item >> 5, q = item & 31;
        int gb = (p >> 3) * 16 + (q >> 1);
        int pk = p & 7;
        int comp = (pk >> 2) & 1;
        const float* a = (const float*)&v0[it];
        const float* b = (const float*)&v1[it];
#pragma unroll
        for (int j = 0; j < 4; ++j) {
            int lane = ((((q & 1) << 2) + j) << 2) + (pk & 3);
            Bs[gb * 66 + lane * 2 + comp] = h2u(a[j], b[j]);
        }
    }
}

// one 32-k chunk (2 ktile16) of warp-tile 64x32 fp16 mma (4 mtiles)
__device__ __forceinline__ void mma_chunk_h(float acc[4][4][4],
                                            const unsigned* __restrict__ Af, int mg0, int gs, int gk0,
                                            const unsigned* __restrict__ Bs, int ng0, int lane)
{
#pragma unroll
    for (int kt = 0; kt < 2; ++kt) {
        uint4 a[4]; uint2 b[4];
#pragma unroll
        for (int mi = 0; mi < 4; ++mi)
            a[mi] = *(const uint4*)&Af[((mg0 + mi) * gs + gk0 + kt) * 132 + lane * 4];
#pragma unroll
        for (int ni = 0; ni < 4; ++ni)
            b[ni] = *(const uint2*)&Bs[((kt << 4) + ng0 + ni) * 66 + lane * 2];
#pragma unroll
        for (int mi = 0; mi < 4; ++mi)
#pragma unroll
            for (int ni = 0; ni < 4; ++ni)
                mma_f16(acc[mi][ni], a[mi].x, a[mi].y, a[mi].z, a[mi].w,
                        b[ni].x, b[ni].y);
    }
}

// same but 2 mtiles (warp tile 32x32) for the 64-row FFN kernel
__device__ __forceinline__ void mma_chunk_h2(float acc[2][4][4],
                                             const unsigned* __restrict__ Af, int mg0, int gs, int gk0,
                                             const unsigned* __restrict__ Bs, int ng0, int lane)
{
#pragma unroll
    for (int kt = 0; kt < 2; ++kt) {
        uint4 a[2]; uint2 b[4];
#pragma unroll
        for (int mi = 0; mi < 2; ++mi)
            a[mi] = *(const uint4*)&Af[((mg0 + mi) * gs + gk0 + kt) * 132 + lane * 4];
#pragma unroll
        for (int ni = 0; ni < 4; ++ni)
            b[ni] = *(const uint2*)&Bs[((kt << 4) + ng0 + ni) * 66 + lane * 2];
#pragma unroll
        for (int mi = 0; mi < 2; ++mi)
#pragma unroll
            for (int ni = 0; ni < 4; ++ni)
                mma_f16(acc[mi][ni], a[mi].x, a[mi].y, a[mi].z, a[mi].w,
                        b[ni].x, b[ni].y);
    }
}

#define ACC_ZERO(acc) \
    _Pragma("unroll") for (int mi = 0; mi < 4; ++mi) \
    _Pragma("unroll") for (int ni = 0; ni < 4; ++ni) \
    _Pragma("unroll") for (int j = 0; j < 4; ++j) acc[mi][ni][j] = 0.f;

#define ACC_ZERO2(acc) \
    _Pragma("unroll") for (int mi = 0; mi < 2; ++mi) \
    _Pragma("unroll") for (int ni = 0; ni < 4; ++ni) \
    _Pragma("unroll") for (int j = 0; j < 4; ++j) acc[mi][ni][j] = 0.f;

// ---------------- fused edge MLP (2 stages fp16; W3 hoisted) ----------------
#define WB_WORDS (4 * 32 * 66)     // 8448 = W1a resident; == Cs (64 groups * 132)
#define CHUNK_WORDS 2112           // streamed chunk
#define EDGE_SMEM ((WB_WORDS + 2 * CHUNK_WORDS + 256) * 4)
#define GEMM_SMEM ((4 * CHUNK_WORDS) * 4)
#define GEMMLN_SMEM ((4 * CHUNK_WORDS + 2 * 128 * 4) * 4)
#define FFN_SMEM ((4224 + 16896 + 2 * CHUNK_WORDS + 2 * 64 * 4) * 4)

__global__ __launch_bounds__(256, 2)
void edge_mlp_tc(const float* __restrict__ hE,
                 const int* __restrict__ esrc,
                 const int* __restrict__ edst,
                 const float* __restrict__ XVs,
                 const float* __restrict__ XVd,
                 const float* __restrict__ W1a, const float* __restrict__ b1,
                 const float* __restrict__ W2,  const float* __restrict__ b2,
                 float* __restrict__ agg, int E)
{
    extern __shared__ unsigned smem_u[];
    unsigned* WB = smem_u;                  // W1a resident; later Cs
    unsigned* Asb[2] = { WB + WB_WORDS, WB + WB_WORDS + CHUNK_WORDS };
    int* s_src = (int*)(WB + WB_WORDS + 2 * CHUNK_WORDS);
    int* s_dst = s_src + 128;

    const int tid = threadIdx.x;
    const int lane = tid & 31;
    const int wid = tid >> 5;
    const int mrow0 = (wid >> 2) * 64;
    const int ncol0 = (wid & 3) * 32;
    const int mg0 = mrow0 >> 4;
    const int ng0 = ncol0 >> 3;
    const int lq = lane >> 2;
    const int lr = lane & 3;
    const int e0 = blockIdx.x * 128;

    if (tid < 128) {
        int e = e0 + tid;
        s_src[tid] = (e < E) ? esrc[e] : -1;
        s_dst[tid] = (e < E) ? edst[e] : -1;
    }

    float4 va[4];
    float4 v0[2], v1[2];
    float acc[4][4][4];

    // ================= stage 1: hE @ W1a (W resident, A ping-pong) ==========
    ACC_ZERO(acc);
#pragma unroll
    for (int c = 0; c < 4; ++c) {
        ldg_Bh(v0, v1, W1a, HD, c * 32, 0, tid);
        sts_Bh(WB + c * CHUNK_WORDS, v0, v1, tid);
    }
    ldg_A(va, hE, HD, e0, E, 0, tid);
    sts_A_h(Asb[0], va, tid);
    __syncthreads();

#pragma unroll
    for (int kc = 0; kc < 4; ++kc) {
        if (kc < 3) ldg_A(va, hE, HD, e0, E, (kc + 1) * 32, tid);
        mma_chunk_h(acc, Asb[kc & 1], mg0, 2, 0, WB + kc * CHUNK_WORDS, ng0, lane);
        if (kc < 3) sts_A_h(Asb[(kc + 1) & 1], va, tid);
        __syncthreads();
    }

    unsigned* Cs = WB;   // alias — all W1a reads are done

    // prefetch W2 chunk 0 (lands while epilogue runs)
    ldg_Bh(v0, v1, W2, HD, 0, 0, tid);

    // epilogue 1: + b1 + XVs[src] + XVd[dst], relu, half2 -> Cs (fp16 A-frag order)
#pragma unroll
    for (int ni = 0; ni < 4; ++ni) {
        int cb = ncol0 + ni * 8 + 2 * lr;
        int pk = cb >> 1;
        int gk = pk >> 3;
        int pkl = pk & 7;
        float b10 = b1[cb], b11 = b1[cb + 1];
#pragma unroll
        for (int mi = 0; mi < 4; ++mi) {
#pragma unroll
            for (int h = 0; h < 2; ++h) {
                int r = mrow0 + mi * 16 + lq + h * 8;
                int ns = s_src[r], nd = s_dst[r];
                float w0 = 0.f, w1 = 0.f;
                if (ns >= 0) {
                    float2 xs = *(const float2*)(XVs + (size_t)ns * HD + cb);
                    float2 xd = *(const float2*)(XVd + (size_t)nd * HD + cb);
                    w0 = acc[mi][ni][h * 2 + 0] + b10 + xs.x + xd.x;
                    w1 = acc[mi][ni][h * 2 + 1] + b11 + xs.y + xd.y;
                }
                int idx = ((mg0 + mi) * 8 + gk) * 132
                        + (((lq << 2) | (pkl & 3)) << 2) + h + (((pkl >> 2) & 1) << 1);
                Cs[idx] = h2u(fmaxf(w0, 0.f), fmaxf(w1, 0.f));
            }
        }
    }
    sts_Bh(Asb[0], v0, v1, tid);
    __syncthreads();

    // ================= stage 2: C1 @ W2 (W ping-pong) =======================
    ACC_ZERO(acc);
#pragma unroll
    for (int kc = 0; kc < 4; ++kc) {
        if (kc < 3) ldg_Bh(v0, v1, W2, HD, (kc + 1) * 32, 0, tid);
        mma_chunk_h(acc, Cs, mg0, 8, kc * 2, Asb[kc & 1], ng0, lane);
        if (kc < 3) sts_Bh(Asb[(kc + 1) & 1], v0, v1, tid);
        __syncthreads();
    }

    // epilogue 2 (final): relu(acc + b2) as half2 row-major (pitch 66) for scatter
#pragma unroll
    for (int ni = 0; ni < 4; ++ni) {
        int cb = ncol0 + ni * 8 + 2 * lr;
        int pk = cb >> 1;
        float b20 = b2[cb], b21 = b2[cb + 1];
#pragma unroll
        for (int mi = 0; mi < 4; ++mi) {
#pragma unroll
            for (int h = 0; h < 2; ++h) {
                int r = mrow0 + mi * 16 + lq + h * 8;
                Cs[r * 66 + pk] = h2u(fmaxf(acc[mi][ni][h * 2 + 0] + b20, 0.f),
                                      fmaxf(acc[mi][ni][h * 2 + 1] + b21, 0.f));
            }
        }
    }
    __syncthreads();

    // cooperative vector scatter of relu(C2): 128 rows x 32 float4
    for (int item = tid; item < 128 * 32; item += 256) {
        int row = item >> 5, q = item & 31;
        int node = s_src[row];
        if (node >= 0) {
            unsigned w0 = Cs[row * 66 + q * 2];
            unsigned w1 = Cs[row * 66 + q * 2 + 1];
            __half2 h0 = *(__half2*)&w0;
            __half2 h1 = *(__half2*)&w1;
            float* p = agg + (size_t)node * HD + q * 4;
            asm volatile("red.global.add.v4.f32 [%0], {%1,%2,%3,%4};"
                         :: "l"(p),
                            "f"(__low2float(h0)), "f"(__high2float(h0)),
                            "f"(__low2float(h1)), "f"(__high2float(h1))
                         : "memory");
        }
    }
}

// ---------------- fp16 node GEMM (layer-0 pre-GEMM only) --------------------
// A@B (no bias). blockIdx.z selects (B,C)/(B2,C2); zbuf zeroed on z==0.
__global__ __launch_bounds__(256, 2)
void gemm_tc(const float* __restrict__ A, const float* __restrict__ B,
             const float* __restrict__ B2,
             float* __restrict__ C, float* __restrict__ C2,
             float* __restrict__ zbuf,
             int M, int N, int K)
{
    extern __shared__ unsigned smem_u[];
    unsigned* Asb[2] = { smem_u, smem_u + CHUNK_WORDS };
    unsigned* Bsb[2] = { smem_u + 2 * CHUNK_WORDS, smem_u + 3 * CHUNK_WORDS };

    const int tid = threadIdx.x;
    const int lane = tid & 31;
    const int wid = tid >> 5;
    const int mrow0 = (wid >> 2) * 64;
    const int ncol0 = (wid & 3) * 32;
    const int mg0 = mrow0 >> 4;
    const int ng0 = ncol0 >> 3;
    const int lq = lane >> 2;
    const int lr = lane & 3;
    const int m0 = blockIdx.y * 128, n0 = blockIdx.x * 128;
    if (blockIdx.z) { B = B2; C = C2; zbuf = nullptr; }

    if (zbuf) {
        const float4 z4 = make_float4(0.f, 0.f, 0.f, 0.f);
        for (int item = tid; item < 128 * 32; item += 256) {
            int row = m0 + (item >> 5);
            if (row < M)
                *(float4*)(zbuf + (size_t)row * HD + (item & 31) * 4) = z4;
        }
    }

    float4 va[4];
    float4 v0[2], v1[2];
    float acc[4][4][4];
    ACC_ZERO(acc);

    const int nkc = K / 32;
    ldg_A(va, A, K, m0, M, 0, tid);
    ldg_Bh(v0, v1, B, N, 0, n0, tid);
    sts_A_h(Asb[0], va, tid);
    sts_Bh(Bsb[0], v0, v1, tid);
    __syncthreads();

    for (int kc = 0; kc < nkc; ++kc) {
        if (kc + 1 < nkc) {
            ldg_A(va, A, K, m0, M, (kc + 1) * 32, tid);
            ldg_Bh(v0, v1, B, N, (kc + 1) * 32, n0, tid);
        }
        mma_chunk_h(acc, Asb[kc & 1], mg0, 2, 0, Bsb[kc & 1], ng0, lane);
        if (kc + 1 < nkc) {
            sts_A_h(Asb[(kc + 1) & 1], va, tid);
            sts_Bh(Bsb[(kc + 1) & 1], v0, v1, tid);
        }
        __syncthreads();
    }

#pragma unroll
    for (int ni = 0; ni < 4; ++ni) {
        int c = n0 + ncol0 + ni * 8 + 2 * lr;
#pragma unroll
        for (int mi = 0; mi < 4; ++mi) {
#pragma unroll
            for (int h = 0; h < 2; ++h) {
                int r = m0 + mrow0 + mi * 16 + lq + h * 8;
                if (r < M) {
                    C[(size_t)r * N + c]     = acc[mi][ni][h * 2 + 0];
                    C[(size_t)r * N + c + 1] = acc[mi][ni][h * 2 + 1];
                }
            }
        }
    }
}

// ---------------- fused GEMM + residual + LayerNorm (N = 128 fixed) ---------
// out = LN(res + (A@B)*inv_deg + bias), register-resident LN.
__global__ __launch_bounds__(256, 2)
void gemm_ln(const float* __restrict__ A, const float* __restrict__ B,
             const float* __restrict__ bias, const float* __restrict__ res,
             const float* __restrict__ deg,
             const float* __restrict__ lng, const float* __restrict__ lnb,
             float* __restrict__ out, int M, int K)
{
    extern __shared__ unsigned smem_u[];
    unsigned* Asb[2] = { smem_u, smem_u + CHUNK_WORDS };
    unsigned* Bsb[2] = { smem_u + 2 * CHUNK_WORDS, smem_u + 3 * CHUNK_WORDS };
    float* s_sum = (float*)(smem_u + 4 * CHUNK_WORDS);  // [128][4]
    float* s_sqs = s_sum + 128 * 4;                     // [128][4]

    const int tid = threadIdx.x;
    const int lane = tid & 31;
    const int wid = tid >> 5;
    const int mrow0 = (wid >> 2) * 64;
    const int ncol0 = (wid & 3) * 32;
    const int mg0 = mrow0 >> 4;
    const int ng0 = ncol0 >> 3;
    const int lq = lane >> 2;
    const int lr = lane & 3;
    const int wc = wid & 3;
    const int m0 = blockIdx.y * 128;

    float4 va[4];
    float4 v0[2], v1[2];
    float acc[4][4][4];
    ACC_ZERO(acc);

    const int nkc = K / 32;
    ldg_A(va, A, K, m0, M, 0, tid);
    ldg_Bh(v0, v1, B, HD, 0, 0, tid);
    sts_A_h(Asb[0], va, tid);
    sts_Bh(Bsb[0], v0, v1, tid);
    __syncthreads();

    for (int kc = 0; kc < nkc; ++kc) {
        if (kc + 1 < nkc) {
            ldg_A(va, A, K, m0, M, (kc + 1) * 32, tid);
            ldg_Bh(v0, v1, B, HD, (kc + 1) * 32, 0, tid);
        }
        mma_chunk_h(acc, Asb[kc & 1], mg0, 2, 0, Bsb[kc & 1], ng0, lane);
        if (kc + 1 < nkc) {
            sts_A_h(Asb[(kc + 1) & 1], va, tid);
            sts_Bh(Bsb[(kc + 1) & 1], v0, v1, tid);
        }
        __syncthreads();
    }

#pragma unroll
    for (int mi = 0; mi < 4; ++mi) {
#pragma unroll
        for (int h = 0; h < 2; ++h) {
            int r = mrow0 + mi * 16 + lq + h * 8;
            int rg = m0 + r;
            float ps = 0.f, pq = 0.f;
            if (rg < M) {
                float id = deg ? (1.f / fmaxf(deg[rg], 1.f)) : 1.f;
#pragma unroll
                for (int ni = 0; ni < 4; ++ni) {
                    int c = ncol0 + ni * 8 + 2 * lr;
                    float2 rr = *(const float2*)(res + (size_t)rg * HD + c);
                    float x0 = rr.x + acc[mi][ni][h * 2 + 0] * id + bias[c];
                    float x1 = rr.y + acc[mi][ni][h * 2 + 1] * id + bias[c + 1];
                    acc[mi][ni][h * 2 + 0] = x0;
                    acc[mi][ni][h * 2 + 1] = x1;
                    ps += x0 + x1;
                    pq += x0 * x0 + x1 * x1;
                }
            }
            ps += __shfl_xor_sync(0xffffffffu, ps, 1);
            pq += __shfl_xor_sync(0xffffffffu, pq, 1);
            ps += __shfl_xor_sync(0xffffffffu, ps, 2);
            pq += __shfl_xor_sync(0xffffffffu, pq, 2);
            if (lr == 0) {
                s_sum[r * 4 + wc] = ps;
                s_sqs[r * 4 + wc] = pq;
            }
        }
    }
    __syncthreads();

#pragma unroll
    for (int mi = 0; mi < 4; ++mi) {
#pragma unroll
        for (int h = 0; h < 2; ++h) {
            int r = mrow0 + mi * 16 + lq + h * 8;
            int rg = m0 + r;
            if (rg < M) {
                float s = s_sum[r * 4 + 0] + s_sum[r * 4 + 1]
                        + s_sum[r * 4 + 2] + s_sum[r * 4 + 3];
                float q = s_sqs[r * 4 + 0] + s_sqs[r * 4 + 1]
                        + s_sqs[r * 4 + 2] + s_sqs[r * 4 + 3];
                float mu = s * (1.f / HD);
                float var = q * (1.f / HD) - mu * mu;
                float inv = rsqrtf(var + 1e-5f);
#pragma unroll
                for (int ni = 0; ni < 4; ++ni) {
                    int c = ncol0 + ni * 8 + 2 * lr;
                    float2 o;
                    o.x = (acc[mi][ni][h * 2 + 0] - mu) * inv * lng[c]     + lnb[c];
                    o.y = (acc[mi][ni][h * 2 + 1] - mu) * inv * lng[c + 1] + lnb[c + 1];
                    *(float2*)(out + (size_t)rg * HD + c) = o;
                }
            }
        }
    }
}

// ---------------- fused FFN + LN + next-layer pre-GEMMs ---------------------
// out = LN(hV + relu(hV@Wi+bi)@Wo + bo); if W1s: xvs = out@W1s, xvd = out@W1d,
// and zero aggz rows for the next layer. One CTA = 64 rows, 8 warps (2x4).
__global__ __launch_bounds__(256, 2)
void ffn_ln(const float* __restrict__ hV,
            const float* __restrict__ Wi, const float* __restrict__ bi,
            const float* __restrict__ Wo, const float* __restrict__ bo,
            const float* __restrict__ lng, const float* __restrict__ lnb,
            float* __restrict__ out,
            const float* __restrict__ W1s, const float* __restrict__ W1d,
            float* __restrict__ xvs, float* __restrict__ xvd,
            float* __restrict__ aggz, int M)
{
    extern __shared__ unsigned smem_u[];
    unsigned* hVt = smem_u;                       // 4224: 64x128 A-frags (32 groups)
    unsigned* Hid = hVt + 4224;                   // 16896: 64x512 A-frags (128 groups)
    unsigned* Bsb[2] = { Hid + 16896, Hid + 16896 + CHUNK_WORDS };
    float* s_sum = (float*)(Hid + 16896 + 2 * CHUNK_WORDS);  // [64][4]
    float* s_sqs = s_sum + 64 * 4;                           // [64][4]

    const int tid = threadIdx.x;
    const int lane = tid & 31;
    const int wid = tid >> 5;
    const int wr = wid >> 2;
    const int wc = wid & 3;
    const int mrow0 = wr * 32;
    const int ncol0 = wc * 32;
    const int mg0 = mrow0 >> 4;
    const int ng0 = ncol0 >> 3;
    const int lq = lane >> 2;
    const int lr = lane & 3;
    const int m0 = blockIdx.x * 64;

    float4 v0[2], v1[2];

    // zero the next layer's scatter accumulator rows (overlaps with loads)
    if (aggz) {
        const float4 z4 = make_float4(0.f, 0.f, 0.f, 0.f);
#pragma unroll
        for (int it = 0; it < 8; ++it) {
            int item = tid + it * 256;
            int row = m0 + (item >> 5);
            if (row < M)
                *(float4*)(aggz + (size_t)row * HD + (item & 31) * 4) = z4;
        }
    }

    // ---- load hV tile (64x128) into A-fragments ----
#pragma unroll
    for (int it = 0; it < 8; ++it) {
        int item = tid + it * 256;
        int row = item >> 5, q = item & 31;
        float4 v = make_float4(0.f, 0.f, 0.f, 0.f);
        if (m0 + row < M)
            v = *(const float4*)(hV + (size_t)(m0 + row) * HD + q * 4);
        int g = ((row >> 4) << 3) + (q >> 2);
        int pk0 = (q & 3) * 2, pk1 = pk0 + 1;
        int off0 = ((((row & 7) << 2) | (pk0 & 3)) << 2) + ((row >> 3) & 1) + (((pk0 >> 2) & 1) << 1);
        int off1 = ((((row & 7) << 2) | (pk1 & 3)) << 2) + ((row >> 3) & 1) + (((pk1 >> 2) & 1) << 1);
        hVt[g * 132 + off0] = h2u(v.x, v.y);
        hVt[g * 132 + off1] = h2u(v.z, v.w);
    }
    ldg_Bh(v0, v1, Wi, 4 * HD, 0, 0, tid);
    sts_Bh(Bsb[0], v0, v1, tid);
    __syncthreads();

    // ---- hidden = relu(hVt @ Wi + bi), 4 N-blocks of 128 ----
    int buf = 0;
#pragma unroll
    for (int nb = 0; nb < 4; ++nb) {
        float acc[2][4][4];
        ACC_ZERO2(acc);
#pragma unroll
        for (int kc = 0; kc < 4; ++kc) {
            bool last = (nb == 3) && (kc == 3);
            if (!last) {
                int nxt = nb * 4 + kc + 1;
                ldg_Bh(v0, v1, Wi, 4 * HD, (nxt & 3) * 32, (nxt >> 2) * 128, tid);
            }
            mma_chunk_h2(acc, hVt, mg0, 8, kc * 2, Bsb[buf], ng0, lane);
            if (!last) sts_Bh(Bsb[buf ^ 1], v0, v1, tid);
            __syncthreads();
            buf ^= 1;
        }
#pragma unroll
        for (int ni = 0; ni < 4; ++ni) {
            int cl = ncol0 + ni * 8 + 2 * lr;
            int c = nb * 128 + cl;
            int pk = c >> 1;
            int gk = pk >> 3;
            int pkl = pk & 7;
            float bb0 = bi[c], bb1 = bi[c + 1];
#pragma unroll
            for (int mi = 0; mi < 2; ++mi) {
#pragma unroll
                for (int h = 0; h < 2; ++h) {
                    int idx = ((mg0 + mi) * 32 + gk) * 132
                            + (((lq << 2) | (pkl & 3)) << 2) + h + (((pkl >> 2) & 1) << 1);
                    Hid[idx] = h2u(fmaxf(acc[mi][ni][h * 2 + 0] + bb0, 0.f),
                                   fmaxf(acc[mi][ni][h * 2 + 1] + bb1, 0.f));
                }
            }
        }
    }
    ldg_Bh(v0, v1, Wo, HD, 0, 0, tid);
    sts_Bh(Bsb[0], v0, v1, tid);
    __syncthreads();

    // ---- acc2 = Hid @ Wo (K = 512, 16 chunks) ----
    float acc2[2][4][4];
    ACC_ZERO2(acc2);
    for (int kc = 0; kc < 16; ++kc) {
        if (kc < 15) ldg_Bh(v0, v1, Wo, HD, (kc + 1) * 32, 0, tid);
        mma_chunk_h2(acc2, Hid, mg0, 32, kc * 2, Bsb[kc & 1], ng0, lane);
        if (kc < 15) sts_Bh(Bsb[(kc + 1) & 1], v0, v1, tid);
        __syncthreads();
    }

    // ---- x = hV + acc2 + bo, register LN partials ----
#pragma unroll
    for (int mi = 0; mi < 2; ++mi) {
#pragma unroll
        for (int h = 0; h < 2; ++h) {
            int r = mrow0 + mi * 16 + lq + h * 8;
            int rg = m0 + r;
            float ps = 0.f, pq = 0.f;
            if (rg < M) {
#pragma unroll
                for (int ni = 0; ni < 4; ++ni) {
                    int c = ncol0 + ni * 8 + 2 * lr;
                    float2 rr = *(const float2*)(hV + (size_t)rg * HD + c);
                    float x0 = rr.x + acc2[mi][ni][h * 2 + 0] + bo[c];
                    float x1 = rr.y + acc2[mi][ni][h * 2 + 1] + bo[c + 1];
                    acc2[mi][ni][h * 2 + 0] = x0;
                    acc2[mi][ni][h * 2 + 1] = x1;
                    ps += x0 + x1;
                    pq += x0 * x0 + x1 * x1;
                }
            }
            ps += __shfl_xor_sync(0xffffffffu, ps, 1);
            pq += __shfl_xor_sync(0xffffffffu, pq, 1);
            ps += __shfl_xor_sync(0xffffffffu, ps, 2);
            pq += __shfl_xor_sync(0xffffffffu, pq, 2);
            if (lr == 0) {
                s_sum[r * 4 + wc] = ps;
                s_sqs[r * 4 + wc] = pq;
            }
        }
    }
    __syncthreads();

    // prefetch W1s chunk 0 while LN finishes
    if (W1s) ldg_Bh(v0, v1, W1s, HD, 0, 0, tid);

    // ---- normalize, store out, and write frags for the pre-GEMMs ----
#pragma unroll
    for (int mi = 0; mi < 2; ++mi) {
#pragma unroll
        for (int h = 0; h < 2; ++h) {
            int r = mrow0 + mi * 16 + lq + h * 8;
            int rg = m0 + r;
            if (rg < M) {
                float s = s_sum[r * 4 + 0] + s_sum[r * 4 + 1]
                        + s_sum[r * 4 + 2] + s_sum[r * 4 + 3];
                float q = s_sqs[r * 4 + 0] + s_sqs[r * 4 + 1]
                        + s_sqs[r * 4 + 2] + s_sqs[r * 4 + 3];
                float mu = s * (1.f / HD);
                float var = q * (1.f / HD) - mu * mu;
                float inv = rsqrtf(var + 1e-5f);
#pragma unroll
                for (int ni = 0; ni < 4; ++ni) {
                    int c = ncol0 + ni * 8 + 2 * lr;
                    float2 o;
                    o.x = (acc2[mi][ni][h * 2 + 0] - mu) * inv * lng[c]     + lnb[c];
                    o.y = (acc2[mi][ni][h * 2 + 1] - mu) * inv * lng[c + 1] + lnb[c + 1];
                    *(float2*)(out + (size_t)rg * HD + c) = o;
                    if (W1s) {
                        int pk = c >> 1;
                        int gk = pk >> 3;
                        int pkl = pk & 7;
                        int idx = ((r >> 4) * 8 + gk) * 132
                                + ((((r & 7) << 2) | (pkl & 3)) << 2)
                                + ((r >> 3) & 1) + (((pkl >> 2) & 1) << 1);
                        hVt[idx] = h2u(o.x, o.y);
                    }
                }
            }
        }
    }
    if (!W1s) return;

    sts_Bh(Bsb[0], v0, v1, tid);
    __syncthreads();

    // ---- xvs = x @ W1s ----
    float accp[2][4][4];
    ACC_ZERO2(accp);
    buf = 0;
#pragma unroll
    for (int kc = 0; kc < 4; ++kc) {
        if (kc < 3) ldg_Bh(v0, v1, W1s, HD, (kc + 1) * 32, 0, tid);
        mma_chunk_h2(accp, hVt, mg0, 8, kc * 2, Bsb[buf], ng0, lane);
        if (kc < 3) sts_Bh(Bsb[buf ^ 1], v0, v1, tid);
        __syncthreads();
        buf ^= 1;
    }
    // prefetch W1d chunk 0
    ldg_Bh(v0, v1, W1d, HD, 0, 0, tid);
#pragma unroll
    for (int mi = 0; mi < 2; ++mi) {
#pragma unroll
        for (int h = 0; h < 2; ++h) {
            int rg = m0 + mrow0 + mi * 16 + lq + h * 8;
            if (rg < M) {
#pragma unroll
                for (int ni = 0; ni < 4; ++ni) {
                    int c = ncol0 + ni * 8 + 2 * lr;
                    float2 o = make_float2(accp[mi][ni][h * 2 + 0], accp[mi][ni][h * 2 + 1]);
                    *(float2*)(xvs + (size_t)rg * HD + c) = o;
                }
            }
        }
    }
    sts_Bh(Bsb[buf], v0, v1, tid);
    __syncthreads();

    // ---- xvd = x @ W1d ----
    ACC_ZERO2(accp);
#pragma unroll
    for (int kc = 0; kc < 4; ++kc) {
        if (kc < 3) ldg_Bh(v0, v1, W1d, HD, (kc + 1) * 32, 0, tid);
        mma_chunk_h2(accp, hVt, mg0, 8, kc * 2, Bsb[buf], ng0, lane);
        if (kc < 3) sts_Bh(Bsb[buf ^ 1], v0, v1, tid);
        __syncthreads();
        buf ^= 1;
    }
#pragma unroll
    for (int mi = 0; mi < 2; ++mi) {
#pragma unroll
        for (int h = 0; h < 2; ++h) {
            int rg = m0 + mrow0 + mi * 16 + lq + h * 8;
            if (rg < M) {
#pragma unroll
                for (int ni = 0; ni < 4; ++ni) {
                    int c = ncol0 + ni * 8 + 2 * lr;
                    float2 o = make_float2(accp[mi][ni][h * 2 + 0], accp[mi][ni][h * 2 + 1]);
                    *(float2*)(xvd + (size_t)rg * HD + c) = o;
                }
            }
        }
    }
}

// ---------------- pooling / heads ------------------------------------------
__global__ void pool_kernel(const float* __restrict__ hV, const int* __restrict__ batch_id,
                            float* __restrict__ pool, float* __restrict__ pcnt, int N)
{
    int i = blockIdx.x * blockDim.x + threadIdx.x;
    if (i < N * HD) {
        int n = i >> 7, c = i & 127;
        atomicAdd(&pool[batch_id[n] * HD + c], hV[i]);
    }
    if (i < N) atomicAdd(&pcnt[batch_id[i]], 1.f);
}

__global__ void head_kernel(const float* __restrict__ pool, const float* __restrict__ pcnt,
                            const float* __restrict__ P1, const float* __restrict__ P2,
                            const float* __restrict__ p2b, float* __restrict__ out)
{
    __shared__ float embs[NB * HD];
    __shared__ float t1[NB * HD];
    int tid = threadIdx.x;
    for (int i = tid; i < NB * HD; i += blockDim.x) {
        int bb = i >> 7;
        embs[i] = pool[i] / fmaxf(pcnt[bb], 1.f);
    }
    __syncthreads();
    for (int i = tid; i < NB * HD; i += blockDim.x) {
        int bb = i >> 7, j = i & 127;
        float s = 0.f;
        for (int k = 0; k < HD; k++) s += embs[bb * HD + k] * P1[k * HD + j];
        t1[i] = fmaxf(s, 0.f);
    }
    __syncthreads();
    for (int i = tid; i < NB * HD; i += blockDim.x) {
        int bb = i >> 7, j = i & 127;
        float s = p2b[j];
        for (int k = 0; k < HD; k++) s += t1[bb * HD + k] * P2[k * HD + j];
        out[i] = s;
    }
}

__global__ void logits_kernel(const float* __restrict__ hV, const int* __restrict__ S,
                              const float* __restrict__ R, const float* __restrict__ rb,
                              float* __restrict__ out, int N)
{
    __shared__ float Rs[HD * NV];
    __shared__ float rbs[NV];
    int tid = threadIdx.x;
    for (int i = tid; i < HD * NV; i += blockDim.x) Rs[i] = R[i];
    if (tid < NV) rbs[tid] = rb[tid];
    __syncthreads();
    int n = blockIdx.x * blockDim.x + tid;
    if (n < N) {
        float a0 = rbs[0], a1 = rbs[1], a2 = rbs[2], a3 = rbs[3];
        const float* h = hV + (size_t)n * HD;
#pragma unroll 8
        for (int k = 0; k < HD; k++) {
            float hv = h[k];
            a0 += hv * Rs[k * NV + 0];
            a1 += hv * Rs[k * NV + 1];
            a2 += hv * Rs[k * NV + 2];
            a3 += hv * Rs[k * NV + 3];
        }
        out[(size_t)n * NV + 0] = a0;
        out[(size_t)n * NV + 1] = a1;
        out[(size_t)n * NV + 2] = a2;
        out[(size_t)n * NV + 3] = a3;
        out[(size_t)N * NV + n] = (float)S[n];
    }
}

// ---------------- launch ----------------------------------------------------
extern "C" void kernel_launch(void* const* d_in, const int* in_sizes, int n_in,
                              void* d_out, int out_size)
{
    const float* h_V  = (const float*)d_in[0];
    const float* h_E  = (const float*)d_in[1];
    const int*   Eidx = (const int*)d_in[2];
    const int*   bid  = (const int*)d_in[3];
    const int*   S    = (const int*)d_in[4];
    const float* W1   = (const float*)d_in[5];
    const float* b1   = (const float*)d_in[6];
    const float* W2   = (const float*)d_in[7];
    const float* b2   = (const float*)d_in[8];
    const float* W3   = (const float*)d_in[9];
    const float* b3   = (const float*)d_in[10];
    const float* ln1g = (const float*)d_in[11];
    const float* ln1b = (const float*)d_in[12];
    const float* Wi   = (const float*)d_in[13];
    const float* bi   = (const float*)d_in[14];
    const float* Wo   = (const float*)d_in[15];
    const float* bo   = (const float*)d_in[16];
    const float* ln2g = (const float*)d_in[17];
    const float* ln2b = (const float*)d_in[18];
    const float* P1   = (const float*)d_in[19];
    const float* P2   = (const float*)d_in[20];
    const float* p2b  = (const float*)d_in[21];
    const float* R    = (const float*)d_in[22];
    const float* rb   = (const float*)d_in[23];

    const int N = in_sizes[0] / HD;
    const int E = in_sizes[2] / 2;
    const int* esrc = Eidx;
    const int* edst = Eidx + E;

    float *p_hV, *p_agg, *p_xvs, *p_xvd, *p_deg, *p_pool, *p_pcnt;
    cudaGetSymbolAddress((void**)&p_hV,   g_hV);
    cudaGetSymbolAddress((void**)&p_agg,  g_agg);
    cudaGetSymbolAddress((void**)&p_xvs,  g_xvs);
    cudaGetSymbolAddress((void**)&p_xvd,  g_xvd);
    cudaGetSymbolAddress((void**)&p_deg,  g_deg);
    cudaGetSymbolAddress((void**)&p_pool, g_pool);
    cudaGetSymbolAddress((void**)&p_pcnt, g_pcnt);

    cudaFuncSetAttribute(edge_mlp_tc,
                         cudaFuncAttributeMaxDynamicSharedMemorySize, EDGE_SMEM);
    cudaFuncSetAttribute(gemm_tc,
                         cudaFuncAttributeMaxDynamicSharedMemorySize, GEMM_SMEM);
    cudaFuncSetAttribute(gemm_ln,
                         cudaFuncAttributeMaxDynamicSharedMemorySize, GEMMLN_SMEM);
    cudaFuncSetAttribute(ffn_ln,
                         cudaFuncAttributeMaxDynamicSharedMemorySize, FFN_SMEM);

    copy_kernel<<<(N * HD + 255) / 256, 256>>>(p_hV, h_V, N * HD);

    zero_kernel<<<(N + 255) / 256, 256>>>(p_deg, N);
    deg_kernel<<<(E + 255) / 256, 256>>>(esrc, p_deg, E);

    const int edge_grid = (E + 127) / 128;
    const int mtiles = (N + 127) / 128;
    const int mtiles2 = (N + 63) / 64;

    // layer-0 pre-GEMMs (+ zero agg): XVs = hV@W1[128:256], XVd = hV@W1[256:384]
    gemm_tc<<<dim3(1, mtiles, 2), 256, GEMM_SMEM>>>(
        p_hV, W1 + (size_t)HD * HD, W1 + (size_t)2 * HD * HD,
        p_xvs, p_xvd, p_agg, N, HD, HD);

    for (int l = 0; l < NL; ++l) {
        const float* W1l = W1 + (size_t)l * 3 * HD * HD;
        const float* W1n = (l + 1 < NL) ? W1 + (size_t)(l + 1) * 3 * HD * HD : nullptr;

        edge_mlp_tc<<<edge_grid, 256, EDGE_SMEM>>>(
            h_E, esrc, edst, p_xvs, p_xvd,
            W1l, b1 + (size_t)l * HD,
            W2 + (size_t)l * HD * HD, b2 + (size_t)l * HD,
            p_agg, E);
        // hV = LN(hV + (agg@W3)/deg + b3)
        gemm_ln<<<dim3(1, mtiles), 256, GEMMLN_SMEM>>>(
            p_agg, W3 + (size_t)l * HD * HD, b3 + (size_t)l * HD,
            p_hV, p_deg,
            ln1g + (size_t)l * HD, ln1b + (size_t)l * HD, p_hV, N, HD);
        // hV = LN(hV + relu(hV@Wi+bi)@Wo + bo); also next-layer XVs/XVd + zero agg
        ffn_ln<<<mtiles2, 256, FFN_SMEM>>>(
            p_hV, Wi + (size_t)l * HD * 4 * HD, bi + (size_t)l * 4 * HD,
            Wo + (size_t)l * 4 * HD * HD, bo + (size_t)l * HD,
            ln2g + (size_t)l * HD, ln2b + (size_t)l * HD, p_hV,
            W1n ? W1n + (size_t)HD * HD : nullptr,
            W1n ? W1n + (size_t)2 * HD * HD : nullptr,
            p_xvs, p_xvd,
            W1n ? p_agg : nullptr, N);
    }

    zero_kernel<<<(NB * HD + 255) / 256, 256>>>(p_pool, NB * HD);
    zero_kernel<<<1, 32>>>(p_pcnt, NB);
    pool_kernel<<<(N * HD + 255) / 256, 256>>>(p_hV, bid, p_pool, p_pcnt, N);

    float* out = (float*)d_out;
    head_kernel<<<1, 256>>>(p_pool, p_pcnt, P1, P2, p2b,
                            out + (size_t)N * NV + N);
    logits_kernel<<<(N + 255) / 256, 256>>>(p_hV, S, R, rb, out, N);
}